// round 10
// baseline (speedup 1.0000x reference)
#include <cuda_runtime.h>
#include <cuda_fp16.h>
#include <math.h>
#include <stdint.h>

#define BB 2
#define CC 128
#define NP 2048
#define KNN 20
#define C2 256

// packed weight-split offsets (halfs)
#define WOFF_Q 0
#define WOFF_K 16384
#define WOFF_V 32768
#define WOFF_M 49152
#define WOFF_1 65536
#define WOFF_2 131072
#define WTOT   163840

// ---------------- scratch arena (floats) ----------------
#define O_QT   0                               // 3 * B*N*C fp32 (q,k,v transposed [b][n][c])
#define O_XX   (O_QT + 3*BB*NP*CC)
#define O_H    (O_XX + BB*NP)                  // B*2C*N fp32 (w1 out, [b][c][n])
#define O_MU   (O_H + BB*C2*NP)
#define O_ISTD (O_MU + C2)
#define O_B1P  (O_ISTD + C2)                   // fused bias b1' (256)
#define O_IDX  (O_B1P + C2)                    // B*N*KNN ints
#define O_XH   (O_IDX + BB*NP*KNN)             // halfs [b][n][c]
#define O_XM   (O_XH + BB*NP*CC/2)
#define O_AVH  (O_XM + BB*NP*CC/2)
#define O_AVM  (O_AVH + BB*NP*CC/2)
#define O_WH   (O_AVM + BB*NP*CC/2)            // packed weight halves
#define O_WM2  (O_WH + WTOT/2)
#define O_PD   (O_WM2 + WTOT/2)
#define TOTALF (O_PD + (size_t)BB*NP*NP)

__device__ __align__(16) float g_buf[TOTALF];

__device__ __forceinline__ uint32_t smem_u32(const void* p) {
    uint32_t a;
    asm("{ .reg .u64 t; cvta.to.shared.u64 t, %1; cvt.u32.u64 %0, t; }" : "=r"(a) : "l"(p));
    return a;
}

#define LDSM4(r, addr) \
    asm volatile("ldmatrix.sync.aligned.m8n8.x4.shared.b16 {%0,%1,%2,%3}, [%4];" \
                 : "=r"((r)[0]), "=r"((r)[1]), "=r"((r)[2]), "=r"((r)[3]) : "r"(addr))

#define MMA16816(acc, a, b0, b1) \
    asm volatile("mma.sync.aligned.m16n8k16.row.col.f32.f16.f16.f32 " \
                 "{%0,%1,%2,%3}, {%4,%5,%6,%7}, {%8,%9}, {%0,%1,%2,%3};" \
                 : "+f"((acc)[0]), "+f"((acc)[1]), "+f"((acc)[2]), "+f"((acc)[3]) \
                 : "r"((a)[0]), "r"((a)[1]), "r"((a)[2]), "r"((a)[3]), "r"(b0), "r"(b1))

// ---------------- xx[b][n] = sum_c x^2 ----------------
__global__ void xx_kernel(const float* __restrict__ x) {
    int i = blockIdx.x * blockDim.x + threadIdx.x;
    if (i >= BB * NP) return;
    int b = i / NP, n = i - b * NP;
    const float* xb = x + (size_t)b * CC * NP + n;
    float s = 0.f;
#pragma unroll 8
    for (int c = 0; c < CC; c++) { float v = xb[(size_t)c * NP]; s = fmaf(v, v, s); }
    g_buf[O_XX + i] = s;
}

// ---------------- transpose + 2-way fp16 split: xT_{h,m}[b][n][c] ----------------
__global__ void prep_kernel(const float* __restrict__ x) {
    __shared__ float ts[32][65];
    int b = blockIdx.z;
    int cbase = blockIdx.y * 32, nbase = blockIdx.x * 64;
    int tid = threadIdx.x;
    __half* xh = reinterpret_cast<__half*>(g_buf + O_XH);
    __half* xm = reinterpret_cast<__half*>(g_buf + O_XM);
#pragma unroll
    for (int i = 0; i < 8; i++) {
        int idx = tid + i * 256;
        int cr = idx >> 6, nn = idx & 63;
        ts[cr][nn] = x[(size_t)b * CC * NP + (size_t)(cbase + cr) * NP + nbase + nn];
    }
    __syncthreads();
#pragma unroll
    for (int i = 0; i < 8; i++) {
        int idx = tid + i * 256;
        int nr = idx >> 5, cc = idx & 31;
        float v = ts[cc][nr];
        __half h1 = __float2half_rn(v);
        __half h2 = __float2half_rn(v - __half2float(h1));
        size_t o = ((size_t)b * NP + nbase + nr) * CC + cbase + cc;
        xh[o] = h1; xm[o] = h2;
    }
}

// ---------------- split all weights to fp16 h/m ----------------
__global__ void wsplit_kernel(const float* __restrict__ wq, const float* __restrict__ wk,
                              const float* __restrict__ wv, const float* __restrict__ wmp,
                              const float* __restrict__ w1, const float* __restrict__ w2) {
    int i = blockIdx.x * 256 + threadIdx.x;
    if (i >= WTOT) return;
    float v;
    if (i < 16384) v = wq[i];
    else if (i < 32768) v = wk[i - 16384];
    else if (i < 49152) v = wv[i - 32768];
    else if (i < 65536) v = wmp[i - 49152];
    else if (i < 131072) v = w1[i - 65536];
    else v = w2[i - 131072];
    __half h = __float2half_rn(v);
    reinterpret_cast<__half*>(g_buf + O_WH)[i] = h;
    reinterpret_cast<__half*>(g_buf + O_WM2)[i] = __float2half_rn(v - __half2float(h));
}

// ---------------- fold wm into w1: F = w1[:,128:]@wm, b1' = b1 + w1[:,128:]@bm ----------------
__global__ void wfuse_kernel(const float* __restrict__ w1, const float* __restrict__ wm,
                             const float* __restrict__ bm, const float* __restrict__ b1) {
    int o = blockIdx.x;            // 0..255
    int c = threadIdx.x;           // 0..127
    float s = 0.f;
#pragma unroll 8
    for (int k = 0; k < 128; k++)
        s = fmaf(w1[o * 256 + 128 + k], wm[k * 128 + c], s);
    __half h = __float2half_rn(s);
    int i = WOFF_1 + o * 256 + 128 + c;
    reinterpret_cast<__half*>(g_buf + O_WH)[i] = h;
    reinterpret_cast<__half*>(g_buf + O_WM2)[i] = __float2half_rn(s - __half2float(h));
    if (c == 0) {
        float bsum = b1[o];
        for (int k = 0; k < 128; k++) bsum = fmaf(w1[o * 256 + 128 + k], bm[k], bsum);
        g_buf[O_B1P + o] = bsum;
    }
}

// ---------------- pd via mma.sync HMMA: D ~ hh + hm + mh (shared fragments) ----------------
#define LDA 264
#define PD_SMEM (1024 + 2 * 128 * LDA * 2)

__global__ void __launch_bounds__(256, 1) pd_mma_kernel() {
    extern __shared__ char ps[];
    float* xxi_s = (float*)ps;
    float* xxj_s = (float*)(ps + 512);
    __half* As = (__half*)(ps + 1024);
    __half* Bs = As + 128 * LDA;

    int tid = threadIdx.x, lane = tid & 31, wid = tid >> 5;
    int b = blockIdx.y;
    int t = blockIdx.x;
    int i = 0;
    while (t >= 16 - i) { t -= 16 - i; i++; }
    int j = i + t;
    int ibase = i * 128, jbase = j * 128;

    const __half* xh = reinterpret_cast<const __half*>(g_buf + O_XH);
    const __half* xm = reinterpret_cast<const __half*>(g_buf + O_XM);

    {
        const __half* srcs[4] = { xh + ((size_t)b * NP + ibase) * CC,
                                  xm + ((size_t)b * NP + ibase) * CC,
                                  xh + ((size_t)b * NP + jbase) * CC,
                                  xm + ((size_t)b * NP + jbase) * CC };
        __half* dsts[4] = { As, As + 128, Bs, Bs + 128 };
#pragma unroll
        for (int s = 0; s < 4; s++) {
            const __half* src = srcs[s];
            __half* dst = dsts[s];
#pragma unroll
            for (int idx = tid; idx < 2048; idx += 256) {
                int row = idx >> 4, ch = idx & 15;
                *(uint4*)(dst + (size_t)row * LDA + ch * 8) =
                    *(const uint4*)(src + (size_t)row * CC + ch * 8);
            }
        }
    }
    if (tid < 128) xxi_s[tid] = g_buf[O_XX + b * NP + ibase + tid];
    else           xxj_s[tid - 128] = g_buf[O_XX + b * NP + jbase + (tid - 128)];
    __syncthreads();

    int mw = wid & 1, nw = wid >> 1;
    uint32_t a_s0 = smem_u32(As + (size_t)(mw * 64) * LDA);
    uint32_t b_s0 = smem_u32(Bs + (size_t)(nw * 32) * LDA);

    float acc[4][4][4];
#pragma unroll
    for (int a1 = 0; a1 < 4; a1++)
#pragma unroll
        for (int a2 = 0; a2 < 4; a2++)
#pragma unroll
            for (int a3 = 0; a3 < 4; a3++) acc[a1][a2][a3] = 0.f;

    int lrow = lane & 15, lcol8 = (lane >> 4) * 8;

#pragma unroll
    for (int k16 = 0; k16 < 8; k16++) {
        int kch = k16 * 16 + lcol8;
        uint32_t ah[4][4], am[4][4], bh[2][4], bm[2][4];
#pragma unroll
        for (int mi = 0; mi < 4; mi++) {
            uint32_t rb = a_s0 + (uint32_t)(((mi * 16 + lrow) * LDA) * 2);
            LDSM4(ah[mi], rb + kch * 2);
            LDSM4(am[mi], rb + (128 + kch) * 2);
        }
#pragma unroll
        for (int nh = 0; nh < 2; nh++) {
            uint32_t rb = b_s0 + (uint32_t)(((nh * 16 + lrow) * LDA) * 2);
            LDSM4(bh[nh], rb + kch * 2);
            LDSM4(bm[nh], rb + (128 + kch) * 2);
        }
#pragma unroll
        for (int mi = 0; mi < 4; mi++)
#pragma unroll
            for (int ni = 0; ni < 4; ni++) {
                uint32_t h0 = bh[ni >> 1][ni & 1], h1 = bh[ni >> 1][2 + (ni & 1)];
                uint32_t m0 = bm[ni >> 1][ni & 1], m1 = bm[ni >> 1][2 + (ni & 1)];
                MMA16816(acc[mi][ni], ah[mi], h0, h1);
                MMA16816(acc[mi][ni], ah[mi], m0, m1);
                MMA16816(acc[mi][ni], am[mi], h0, h1);
            }
    }

    int g = lane >> 2, q = lane & 3;
    float* pdb = g_buf + O_PD + (size_t)b * NP * NP;
#pragma unroll
    for (int mi = 0; mi < 4; mi++)
#pragma unroll
        for (int ni = 0; ni < 4; ni++) {
            int r0 = mw * 64 + mi * 16 + g;
            int c0 = nw * 32 + ni * 8 + q * 2;
            float xj0 = xxj_s[c0], xj1 = xxj_s[c0 + 1];
            float xi0 = xxi_s[r0], xi1 = xxi_s[r0 + 8];
            float2 v01, v23;
            v01.x = 2.f * acc[mi][ni][0] - xi0 - xj0;
            v01.y = 2.f * acc[mi][ni][1] - xi0 - xj1;
            v23.x = 2.f * acc[mi][ni][2] - xi1 - xj0;
            v23.y = 2.f * acc[mi][ni][3] - xi1 - xj1;
            *(float2*)(pdb + (size_t)(ibase + r0) * NP + jbase + c0) = v01;
            *(float2*)(pdb + (size_t)(ibase + r0 + 8) * NP + jbase + c0) = v23;
        }

    __syncthreads();
    if (ibase != jbase) {
        float* patch = (float*)(ps + 1024) + (size_t)wid * 32 * 68;
#pragma unroll
        for (int mi = 0; mi < 4; mi++)
#pragma unroll
            for (int ni = 0; ni < 4; ni++) {
                int rl = mi * 16 + g;
                int cl = ni * 8 + q * 2;
                int r0 = mw * 64 + rl, c0 = nw * 32 + cl;
                float xj0 = xxj_s[c0], xj1 = xxj_s[c0 + 1];
                float xi0 = xxi_s[r0], xi1 = xxi_s[r0 + 8];
                patch[(cl + 0) * 68 + rl]     = 2.f * acc[mi][ni][0] - xi0 - xj0;
                patch[(cl + 1) * 68 + rl]     = 2.f * acc[mi][ni][1] - xi0 - xj1;
                patch[(cl + 0) * 68 + rl + 8] = 2.f * acc[mi][ni][2] - xi1 - xj0;
                patch[(cl + 1) * 68 + rl + 8] = 2.f * acc[mi][ni][3] - xi1 - xj1;
            }
        __syncwarp();
#pragma unroll
        for (int cc = 0; cc < 32; cc++) {
            float2 val = *(float2*)(patch + cc * 68 + lane * 2);
            *(float2*)(pdb + (size_t)(jbase + nw * 32 + cc) * NP + ibase + mw * 64 + lane * 2) = val;
        }
    }
}

// ---------------- HMMA conv1x1 (shared-fragment mainloop) ----------------
// MODE 0=QKV (out fp32 [b][n][c])  2=W1-fused (K=256: x then av, out fp32 [b][o][n])
// 3=W2 (K=256, fused bn+relu load from O_H fp32, residual, out fp32)
#define CLDA 264
#define CONV_SMEM (2 * 128 * CLDA * 2)

template<int MODE>
__global__ void __launch_bounds__(256, 1) conv_mma(const float* __restrict__ bias0,
                                                   const float* __restrict__ bias1,
                                                   const float* __restrict__ bias2,
                                                   const float* __restrict__ resid,
                                                   float* __restrict__ outp) {
    extern __shared__ char cs[];
    __half* As = (__half*)cs;
    __half* Bs = As + 128 * CLDA;
    int tid = threadIdx.x, lane = tid & 31, wid = tid >> 5;
    int b = blockIdx.z, nbase = blockIdx.x * 128;
    int yb = blockIdx.y;

    const __half* WH = reinterpret_cast<const __half*>(g_buf + O_WH);
    const __half* WM = reinterpret_cast<const __half*>(g_buf + O_WM2);
    int woff, wstride, obase = 0;
    if (MODE == 0)      { woff = yb * 16384; wstride = 128; }
    else if (MODE == 2) { woff = WOFF_1 + yb * 128 * 256; wstride = 256; obase = yb * 128; }
    else                { woff = WOFF_2; wstride = 256; }
    const int KCH = (MODE >= 2) ? 2 : 1;

    float acc[4][4][4];
#pragma unroll
    for (int a1 = 0; a1 < 4; a1++)
#pragma unroll
        for (int a2 = 0; a2 < 4; a2++)
#pragma unroll
            for (int a3 = 0; a3 < 4; a3++) acc[a1][a2][a3] = 0.f;

    int mw = wid & 1, nw = wid >> 1;
    int lrow = lane & 15, lcol8 = (lane >> 4) * 8;
    uint32_t a_s0 = smem_u32(As + (size_t)(mw * 64) * CLDA);
    uint32_t b_s0 = smem_u32(Bs + (size_t)(nw * 32) * CLDA);

#pragma unroll
    for (int kc = 0; kc < KCH; kc++) {
        const __half* wsh = WH + woff + kc * 128;
        const __half* wsm = WM + woff + kc * 128;
#pragma unroll
        for (int idx = tid; idx < 2048; idx += 256) {
            int row = idx >> 4, ch = idx & 15;
            *(uint4*)(As + (size_t)row * CLDA + ch * 8) =
                *(const uint4*)(wsh + (size_t)row * wstride + ch * 8);
            *(uint4*)(As + (size_t)row * CLDA + 128 + ch * 8) =
                *(const uint4*)(wsm + (size_t)row * wstride + ch * 8);
        }
        if (MODE == 3) {
            // fused bn + relu + fp16-split transpose load from h[b][c][n]
            const float* hsrc = g_buf + O_H + (size_t)b * C2 * NP + (size_t)(kc * 128) * NP;
            const float* gam = bias1;
            const float* bet = bias2;
#pragma unroll 4
            for (int idx = tid; idx < 4096; idx += 256) {
                int c = idx >> 5, n4 = (idx & 31) * 4;
                int cg = kc * 128 + c;
                float mu = g_buf[O_MU + cg], is = g_buf[O_ISTD + cg];
                float ga = gam[cg], be = bet[cg];
                float4 v4 = *(const float4*)(hsrc + (size_t)c * NP + nbase + n4);
                float vv[4] = {v4.x, v4.y, v4.z, v4.w};
#pragma unroll
                for (int u = 0; u < 4; u++) {
                    float v = fmaxf(fmaf((vv[u] - mu) * is, ga, be), 0.f);
                    __half hh = __float2half_rn(v);
                    Bs[(size_t)(n4 + u) * CLDA + c] = hh;
                    Bs[(size_t)(n4 + u) * CLDA + 128 + c] = __float2half_rn(v - __half2float(hh));
                }
            }
        } else {
            const __half *bh, *bm;
            if (MODE == 0) { bh = (const __half*)(g_buf + O_XH); bm = (const __half*)(g_buf + O_XM); }
            else {
                if (kc == 0) { bh = (const __half*)(g_buf + O_XH); bm = (const __half*)(g_buf + O_XM); }
                else         { bh = (const __half*)(g_buf + O_AVH); bm = (const __half*)(g_buf + O_AVM); }
            }
            const __half* bhp = bh + (size_t)(b * NP + nbase) * 128;
            const __half* bmp = bm + (size_t)(b * NP + nbase) * 128;
#pragma unroll
            for (int idx = tid; idx < 2048; idx += 256) {
                int row = idx >> 4, ch = idx & 15;
                *(uint4*)(Bs + (size_t)row * CLDA + ch * 8) =
                    *(const uint4*)(bhp + (size_t)row * 128 + ch * 8);
                *(uint4*)(Bs + (size_t)row * CLDA + 128 + ch * 8) =
                    *(const uint4*)(bmp + (size_t)row * 128 + ch * 8);
            }
        }
        __syncthreads();

#pragma unroll
        for (int k16 = 0; k16 < 8; k16++) {
            int kch = k16 * 16 + lcol8;
            uint32_t ah[4][4], am[4][4], bh[2][4], bm[2][4];
#pragma unroll
            for (int mi = 0; mi < 4; mi++) {
                uint32_t rb = a_s0 + (uint32_t)(((mi * 16 + lrow) * CLDA) * 2);
                LDSM4(ah[mi], rb + kch * 2);
                LDSM4(am[mi], rb + (128 + kch) * 2);
            }
#pragma unroll
            for (int nh = 0; nh < 2; nh++) {
                uint32_t rb = b_s0 + (uint32_t)(((nh * 16 + lrow) * CLDA) * 2);
                LDSM4(bh[nh], rb + kch * 2);
                LDSM4(bm[nh], rb + (128 + kch) * 2);
            }
#pragma unroll
            for (int mi = 0; mi < 4; mi++)
#pragma unroll
                for (int ni = 0; ni < 4; ni++) {
                    uint32_t h0 = bh[ni >> 1][ni & 1], h1 = bh[ni >> 1][2 + (ni & 1)];
                    uint32_t m0 = bm[ni >> 1][ni & 1], m1 = bm[ni >> 1][2 + (ni & 1)];
                    MMA16816(acc[mi][ni], ah[mi], h0, h1);
                    MMA16816(acc[mi][ni], ah[mi], m0, m1);
                    MMA16816(acc[mi][ni], am[mi], h0, h1);
                }
        }
        __syncthreads();
    }

    int g = lane >> 2, q = lane & 3;
    if (MODE == 0) {
        const float* bias_ = (yb == 0 ? bias0 : yb == 1 ? bias1 : bias2);
        float* patch = (float*)cs + (size_t)wid * 32 * 68;
#pragma unroll
        for (int mi = 0; mi < 4; mi++)
#pragma unroll
            for (int ni = 0; ni < 4; ni++) {
                int rl = mi * 16 + g;
                int cl = ni * 8 + q * 2;
                float bs0 = bias_[mw * 64 + rl], bs1 = bias_[mw * 64 + rl + 8];
                patch[(cl + 0) * 68 + rl]     = acc[mi][ni][0] + bs0;
                patch[(cl + 1) * 68 + rl]     = acc[mi][ni][1] + bs0;
                patch[(cl + 0) * 68 + rl + 8] = acc[mi][ni][2] + bs1;
                patch[(cl + 1) * 68 + rl + 8] = acc[mi][ni][3] + bs1;
            }
        __syncwarp();
        float* Y = g_buf + O_QT + (size_t)yb * BB * NP * CC;
#pragma unroll
        for (int r = 0; r < 32; r++) {
            int n = nbase + nw * 32 + r;
            *(float2*)(Y + ((size_t)b * NP + n) * CC + mw * 64 + lane * 2) =
                *(float2*)(patch + r * 68 + lane * 2);
        }
    } else {
        const float* bias_ = bias0;
        float* Yb = outp + (size_t)b * ((MODE == 2) ? C2 * NP : CC * NP);
#pragma unroll
        for (int mi = 0; mi < 4; mi++)
#pragma unroll
            for (int ni = 0; ni < 4; ni++) {
                int r0 = obase + mw * 64 + mi * 16 + g;
                int c0 = nbase + nw * 32 + ni * 8 + q * 2;
                float bs0 = bias_[r0], bs1 = bias_[r0 + 8];
                float2 v01, v23;
                v01.x = acc[mi][ni][0] + bs0; v01.y = acc[mi][ni][1] + bs0;
                v23.x = acc[mi][ni][2] + bs1; v23.y = acc[mi][ni][3] + bs1;
                if (MODE == 3) {
                    const float* rb = resid + (size_t)b * CC * NP;
                    v01.x += rb[(size_t)r0 * NP + c0];
                    v01.y += rb[(size_t)r0 * NP + c0 + 1];
                    v23.x += rb[(size_t)(r0 + 8) * NP + c0];
                    v23.y += rb[(size_t)(r0 + 8) * NP + c0 + 1];
                }
                *(float2*)(Yb + (size_t)r0 * NP + c0) = v01;
                *(float2*)(Yb + (size_t)(r0 + 8) * NP + c0) = v23;
            }
    }
}

// ---------------- warp-per-row top-20 ----------------
#define TOPK_SMEM (8 * 2048 * 4)
__global__ void __launch_bounds__(256) topk_kernel() {
    extern __shared__ float srows[];
    const unsigned FULL = 0xffffffffu;
    int tid = threadIdx.x, lane = tid & 31, wid = tid >> 5;
    int rowbase = blockIdx.x * 8;
    const float4* g4 = (const float4*)(g_buf + O_PD + (size_t)rowbase * NP);
    float4* s4 = (float4*)srows;
#pragma unroll
    for (int i = tid; i < 8 * 512; i += 256) s4[i] = g4[i];
    __syncthreads();

    float* s = srows + wid * 2048 + lane * 64;
    float bv = -3.4e38f; int bi = 0;
#pragma unroll
    for (int k4 = 0; k4 < 16; k4++) {
        float4 vv = *(float4*)(s + k4 * 4);
        if (vv.x > bv) { bv = vv.x; bi = k4 * 4 + 0; }
        if (vv.y > bv) { bv = vv.y; bi = k4 * 4 + 1; }
        if (vv.z > bv) { bv = vv.z; bi = k4 * 4 + 2; }
        if (vv.w > bv) { bv = vv.w; bi = k4 * 4 + 3; }
    }
    int gbase = lane * 64;
    int* idxout = reinterpret_cast<int*>(g_buf + O_IDX) + (size_t)(rowbase + wid) * KNN;

    for (int it = 0; it < KNN; it++) {
        float cv = bv; int ci = gbase + bi;
#pragma unroll
        for (int off = 16; off; off >>= 1) {
            float ov = __shfl_down_sync(FULL, cv, off);
            int oi = __shfl_down_sync(FULL, ci, off);
            if (ov > cv || (ov == cv && oi < ci)) { cv = ov; ci = oi; }
        }
        ci = __shfl_sync(FULL, ci, 0);
        if (lane == 0) idxout[it] = ci;
        if ((ci >> 6) == lane) {
            s[ci & 63] = -3.4e38f;
            bv = -3.4e38f; bi = 0;
#pragma unroll
            for (int k4 = 0; k4 < 16; k4++) {
                float4 vv = *(float4*)(s + k4 * 4);
                if (vv.x > bv) { bv = vv.x; bi = k4 * 4 + 0; }
                if (vv.y > bv) { bv = vv.y; bi = k4 * 4 + 1; }
                if (vv.z > bv) { bv = vv.z; bi = k4 * 4 + 2; }
                if (vv.w > bv) { bv = vv.w; bi = k4 * 4 + 3; }
            }
        }
    }
}

// ---------------- sparse mutual-kNN attention: one warp per (b,n) ----------------
__global__ void attn_kernel() {
    const unsigned FULL = 0xffffffffu;
    int gwarp = (blockIdx.x * blockDim.x + threadIdx.x) >> 5;
    int lane = threadIdx.x & 31;
    int b = gwarp / NP, n = gwarp - b * NP;

    const float* qT = g_buf + O_QT;
    const float* kT = g_buf + O_QT + BB * NP * CC;
    const float* vT = g_buf + O_QT + 2 * BB * NP * CC;
    const int* idx = reinterpret_cast<const int*>(g_buf + O_IDX);

    const float* qrow = qT + ((size_t)b * NP + n) * CC;
    float q0 = qrow[lane], q1 = qrow[lane + 32], q2 = qrow[lane + 64], q3 = qrow[lane + 96];

    int mj = 0, act = 0;
    if (lane < KNN) {
        mj = idx[(b * NP + n) * KNN + lane];
        const int* lst = idx + (size_t)(b * NP + mj) * KNN;
#pragma unroll
        for (int tt = 0; tt < KNN; tt++) act |= (lst[tt] == n);
    }
    unsigned amask = __ballot_sync(FULL, act);

    float sc[4] = {0.f, 0.f, 0.f, 0.f};
    for (int jj = 0; jj < KNN; jj++) {
        if (!((amask >> jj) & 1)) continue;
        int m = __shfl_sync(FULL, mj, jj);
        const float* krow = kT + ((size_t)b * NP + m) * CC;
        float p0 = q0 * krow[lane], p1 = q1 * krow[lane + 32];
        float p2 = q2 * krow[lane + 64], p3 = q3 * krow[lane + 96];
#pragma unroll
        for (int off = 16; off; off >>= 1) {
            p0 += __shfl_xor_sync(FULL, p0, off);
            p1 += __shfl_xor_sync(FULL, p1, off);
            p2 += __shfl_xor_sync(FULL, p2, off);
            p3 += __shfl_xor_sync(FULL, p3, off);
        }
        if (lane == jj) { sc[0] = p0; sc[1] = p1; sc[2] = p2; sc[3] = p3; }
    }

    const float scale = 0.17677669529663687f;
    bool live = (lane < KNN) && ((amask >> lane) & 1);
    float p[4];
#pragma unroll
    for (int hh = 0; hh < 4; hh++) {
        float v = live ? sc[hh] * scale : -3.4e38f;
        float mx = v;
#pragma unroll
        for (int off = 16; off; off >>= 1) mx = fmaxf(mx, __shfl_xor_sync(FULL, mx, off));
        float e = live ? expf(v - mx) : 0.f;
        float sm = e;
#pragma unroll
        for (int off = 16; off; off >>= 1) sm += __shfl_xor_sync(FULL, sm, off);
        p[hh] = e / sm;
    }

    float a0 = 0.f, a1 = 0.f, a2 = 0.f, a3 = 0.f;
    for (int jj = 0; jj < KNN; jj++) {
        if (!((amask >> jj) & 1)) continue;
        int m = __shfl_sync(FULL, mj, jj);
        float w0 = __shfl_sync(FULL, p[0], jj);
        float w1 = __shfl_sync(FULL, p[1], jj);
        float w2 = __shfl_sync(FULL, p[2], jj);
        float w3 = __shfl_sync(FULL, p[3], jj);
        const float* vrow = vT + ((size_t)b * NP + m) * CC;
        a0 = fmaf(w0, vrow[lane], a0);
        a1 = fmaf(w1, vrow[lane + 32], a1);
        a2 = fmaf(w2, vrow[lane + 64], a2);
        a3 = fmaf(w3, vrow[lane + 96], a3);
    }
    __half* avh = (__half*)(g_buf + O_AVH);
    __half* avm = (__half*)(g_buf + O_AVM);
    size_t o = ((size_t)b * NP + n) * CC;
    float vals[4] = {a0, a1, a2, a3};
#pragma unroll
    for (int c = 0; c < 4; c++) {
        __half hh = __float2half_rn(vals[c]);
        avh[o + c * 32 + lane] = hh;
        avm[o + c * 32 + lane] = __float2half_rn(vals[c] - __half2float(hh));
    }
}

// ---------------- batchnorm statistics ----------------
__global__ void bn_stats_kernel() {
    __shared__ float ss[256], ss2[256];
    int c = blockIdx.x, tid = threadIdx.x;
    float s = 0.f, s2 = 0.f;
    for (int bn = tid; bn < BB * NP; bn += 256) {
        int b = bn >> 11, n = bn & (NP - 1);
        float v = g_buf[O_H + (size_t)b * C2 * NP + (size_t)c * NP + n];
        s += v; s2 = fmaf(v, v, s2);
    }
    ss[tid] = s; ss2[tid] = s2;
    __syncthreads();
    for (int off = 128; off; off >>= 1) {
        if (tid < off) { ss[tid] += ss[tid + off]; ss2[tid] += ss2[tid + off]; }
        __syncthreads();
    }
    if (tid == 0) {
        float inv = 1.f / (BB * NP);
        float mu = ss[0] * inv;
        float var = ss2[0] * inv - mu * mu;
        g_buf[O_MU + c] = mu;
        g_buf[O_ISTD + c] = rsqrtf(var + 1e-5f);
    }
}

// ---------------- launch ----------------
extern "C" void kernel_launch(void* const* d_in, const int* in_sizes, int n_in,
                              void* d_out, int out_size) {
    (void)in_sizes; (void)n_in; (void)out_size;
    const float* x     = (const float*)d_in[0];
    const float* wq    = (const float*)d_in[1];
    const float* bq    = (const float*)d_in[2];
    const float* wk    = (const float*)d_in[3];
    const float* bk    = (const float*)d_in[4];
    const float* wv    = (const float*)d_in[5];
    const float* bv    = (const float*)d_in[6];
    const float* wm    = (const float*)d_in[7];
    const float* bm    = (const float*)d_in[8];
    const float* w1    = (const float*)d_in[9];
    const float* b1    = (const float*)d_in[10];
    const float* gamma = (const float*)d_in[11];
    const float* beta  = (const float*)d_in[12];
    const float* w2    = (const float*)d_in[13];
    const float* b2    = (const float*)d_in[14];
    float* out = (float*)d_out;

    float* base = nullptr;
    cudaGetSymbolAddress((void**)&base, g_buf);
    float* p_h = base + O_H;
    float* p_b1p = base + O_B1P;

    static cudaStream_t s2 = nullptr, s3 = nullptr;
    static cudaEvent_t evFork = nullptr, evPrep = nullptr, evXX = nullptr,
                       evQKV = nullptr, evW = nullptr;
    if (s2 == nullptr) {
        cudaStreamCreateWithFlags(&s2, cudaStreamNonBlocking);
        cudaStreamCreateWithFlags(&s3, cudaStreamNonBlocking);
        cudaEventCreateWithFlags(&evFork, cudaEventDisableTiming);
        cudaEventCreateWithFlags(&evPrep, cudaEventDisableTiming);
        cudaEventCreateWithFlags(&evXX, cudaEventDisableTiming);
        cudaEventCreateWithFlags(&evQKV, cudaEventDisableTiming);
        cudaEventCreateWithFlags(&evW, cudaEventDisableTiming);
    }

    cudaFuncSetAttribute(pd_mma_kernel, cudaFuncAttributeMaxDynamicSharedMemorySize, PD_SMEM);
    cudaFuncSetAttribute(conv_mma<0>, cudaFuncAttributeMaxDynamicSharedMemorySize, CONV_SMEM);
    cudaFuncSetAttribute(conv_mma<2>, cudaFuncAttributeMaxDynamicSharedMemorySize, CONV_SMEM);
    cudaFuncSetAttribute(conv_mma<3>, cudaFuncAttributeMaxDynamicSharedMemorySize, CONV_SMEM);
    cudaFuncSetAttribute(topk_kernel, cudaFuncAttributeMaxDynamicSharedMemorySize, TOPK_SMEM);

    // fork point
    cudaEventRecord(evFork, 0);
    cudaStreamWaitEvent(s2, evFork, 0);
    cudaStreamWaitEvent(s3, evFork, 0);

    // s2: weight split -> (wait prep) qkv conv -> weight fuse
    wsplit_kernel<<<(WTOT + 255) / 256, 256, 0, s2>>>(wq, wk, wv, wm, w1, w2);
    // s3: xx
    xx_kernel<<<(BB * NP + 255) / 256, 256, 0, s3>>>(x);
    cudaEventRecord(evXX, s3);
    // main: prep
    prep_kernel<<<dim3(NP / 64, CC / 32, BB), 256>>>(x);
    cudaEventRecord(evPrep, 0);

    cudaStreamWaitEvent(s2, evPrep, 0);
    conv_mma<0><<<dim3(NP / 128, 3, BB), 256, CONV_SMEM, s2>>>(bq, bk, bv, nullptr, nullptr);
    cudaEventRecord(evQKV, s2);
    wfuse_kernel<<<256, 128, 0, s2>>>(w1, wm, bm, b1);
    cudaEventRecord(evW, s2);

    // main: pd -> topk (needs prep + xx)
    cudaStreamWaitEvent(0, evXX, 0);
    pd_mma_kernel<<<dim3(136, BB), 256, PD_SMEM>>>();
    topk_kernel<<<BB * NP / 8, 256, TOPK_SMEM>>>();

    cudaStreamWaitEvent(0, evQKV, 0);
    attn_kernel<<<BB * NP / 8, 256>>>();

    cudaStreamWaitEvent(0, evW, 0);
    conv_mma<2><<<dim3(NP / 128, 2, BB), 256, CONV_SMEM>>>(p_b1p, nullptr, nullptr, nullptr, p_h);

    bn_stats_kernel<<<C2, 256>>>();

    // final conv with fused bn+relu input, residual add
    conv_mma<3><<<dim3(NP / 128, 1, BB), 256, CONV_SMEM>>>(b2, gamma, beta, x, out);
}

// round 14
// speedup vs baseline: 1.1044x; 1.1044x over previous
#include <cuda_runtime.h>
#include <cuda_fp16.h>
#include <math.h>
#include <stdint.h>

#define BB 2
#define CC 128
#define NP 2048
#define KNN 20
#define C2 256

// packed weight-split offsets (halfs)
#define WOFF_Q 0
#define WOFF_K 16384
#define WOFF_V 32768
#define WOFF_M 49152
#define WOFF_1 65536
#define WOFF_2 131072
#define WTOT   163840

// ---------------- scratch arena (floats) ----------------
#define O_QT   0                               // 3 * B*N*C fp32 (q,k,v transposed [b][n][c])
#define O_XX   (O_QT + 3*BB*NP*CC)
#define O_H    (O_XX + BB*NP)                  // B*2C*N fp32 (w1 out, [b][c][n])
#define O_MU   (O_H + BB*C2*NP)
#define O_ISTD (O_MU + C2)
#define O_B1P  (O_ISTD + C2)                   // fused bias b1' (256)
#define O_IDX  (O_B1P + C2)                    // B*N*KNN ints
#define O_XH   (O_IDX + BB*NP*KNN)             // halfs [b][n][c]
#define O_XM   (O_XH + BB*NP*CC/2)
#define O_AVH  (O_XM + BB*NP*CC/2)
#define O_AVM  (O_AVH + BB*NP*CC/2)
#define O_H2H  (O_AVM + BB*NP*CC/2)            // halfs [b][n][2C]
#define O_H2M  (O_H2H + BB*NP*C2/2)
#define O_WH   (O_H2M + BB*NP*C2/2)            // packed weight halves
#define O_WM2  (O_WH + WTOT/2)
#define O_PD   (O_WM2 + WTOT/2)
#define TOTALF (O_PD + (size_t)BB*NP*NP)

__device__ __align__(16) float g_buf[TOTALF];

__device__ __forceinline__ uint32_t smem_u32(const void* p) {
    uint32_t a;
    asm("{ .reg .u64 t; cvta.to.shared.u64 t, %1; cvt.u32.u64 %0, t; }" : "=r"(a) : "l"(p));
    return a;
}

#define LDSM4(r, addr) \
    asm volatile("ldmatrix.sync.aligned.m8n8.x4.shared.b16 {%0,%1,%2,%3}, [%4];" \
                 : "=r"((r)[0]), "=r"((r)[1]), "=r"((r)[2]), "=r"((r)[3]) : "r"(addr))

#define MMA16816(acc, a, b0, b1) \
    asm volatile("mma.sync.aligned.m16n8k16.row.col.f32.f16.f16.f32 " \
                 "{%0,%1,%2,%3}, {%4,%5,%6,%7}, {%8,%9}, {%0,%1,%2,%3};" \
                 : "+f"((acc)[0]), "+f"((acc)[1]), "+f"((acc)[2]), "+f"((acc)[3]) \
                 : "r"((a)[0]), "r"((a)[1]), "r"((a)[2]), "r"((a)[3]), "r"(b0), "r"(b1))

// ---------------- xx[b][n] = sum_c x^2 ----------------
__global__ void xx_kernel(const float* __restrict__ x) {
    int i = blockIdx.x * blockDim.x + threadIdx.x;
    if (i >= BB * NP) return;
    int b = i / NP, n = i - b * NP;
    const float* xb = x + (size_t)b * CC * NP + n;
    float s = 0.f;
#pragma unroll 8
    for (int c = 0; c < CC; c++) { float v = xb[(size_t)c * NP]; s = fmaf(v, v, s); }
    g_buf[O_XX + i] = s;
}

// ---------------- transpose + 2-way fp16 split: xT_{h,m}[b][n][c] ----------------
__global__ void prep_kernel(const float* __restrict__ x) {
    __shared__ float ts[32][65];
    int b = blockIdx.z;
    int cbase = blockIdx.y * 32, nbase = blockIdx.x * 64;
    int tid = threadIdx.x;
    __half* xh = reinterpret_cast<__half*>(g_buf + O_XH);
    __half* xm = reinterpret_cast<__half*>(g_buf + O_XM);
#pragma unroll
    for (int i = 0; i < 8; i++) {
        int idx = tid + i * 256;
        int cr = idx >> 6, nn = idx & 63;
        ts[cr][nn] = x[(size_t)b * CC * NP + (size_t)(cbase + cr) * NP + nbase + nn];
    }
    __syncthreads();
#pragma unroll
    for (int i = 0; i < 8; i++) {
        int idx = tid + i * 256;
        int nr = idx >> 5, cc = idx & 31;
        float v = ts[cc][nr];
        __half h1 = __float2half_rn(v);
        __half h2 = __float2half_rn(v - __half2float(h1));
        size_t o = ((size_t)b * NP + nbase + nr) * CC + cbase + cc;
        xh[o] = h1; xm[o] = h2;
    }
}

// ---------------- split all weights to fp16 h/m ----------------
__global__ void wsplit_kernel(const float* __restrict__ wq, const float* __restrict__ wk,
                              const float* __restrict__ wv, const float* __restrict__ wmp,
                              const float* __restrict__ w1, const float* __restrict__ w2) {
    int i = blockIdx.x * 256 + threadIdx.x;
    if (i >= WTOT) return;
    float v;
    if (i < 16384) v = wq[i];
    else if (i < 32768) v = wk[i - 16384];
    else if (i < 49152) v = wv[i - 32768];
    else if (i < 65536) v = wmp[i - 49152];
    else if (i < 131072) v = w1[i - 65536];
    else v = w2[i - 131072];
    __half h = __float2half_rn(v);
    reinterpret_cast<__half*>(g_buf + O_WH)[i] = h;
    reinterpret_cast<__half*>(g_buf + O_WM2)[i] = __float2half_rn(v - __half2float(h));
}

// ---------------- fold wm into w1: F = w1[:,128:]@wm, b1' = b1 + w1[:,128:]@bm ----------------
__global__ void wfuse_kernel(const float* __restrict__ w1, const float* __restrict__ wm,
                             const float* __restrict__ bm, const float* __restrict__ b1) {
    int o = blockIdx.x;            // 0..255
    int c = threadIdx.x;           // 0..127
    float s = 0.f;
#pragma unroll 8
    for (int k = 0; k < 128; k++)
        s = fmaf(w1[o * 256 + 128 + k], wm[k * 128 + c], s);
    __half h = __float2half_rn(s);
    int i = WOFF_1 + o * 256 + 128 + c;
    reinterpret_cast<__half*>(g_buf + O_WH)[i] = h;
    reinterpret_cast<__half*>(g_buf + O_WM2)[i] = __float2half_rn(s - __half2float(h));
    if (c == 0) {
        float bsum = b1[o];
        for (int k = 0; k < 128; k++) bsum = fmaf(w1[o * 256 + 128 + k], bm[k], bsum);
        g_buf[O_B1P + o] = bsum;
    }
}

// ---------------- pd via mma.sync HMMA: D ~ hh + hm + mh (shared fragments) ----------------
#define LDA 264
#define PD_SMEM (1024 + 2 * 128 * LDA * 2)

__global__ void __launch_bounds__(256, 1) pd_mma_kernel() {
    extern __shared__ char ps[];
    float* xxi_s = (float*)ps;
    float* xxj_s = (float*)(ps + 512);
    __half* As = (__half*)(ps + 1024);
    __half* Bs = As + 128 * LDA;

    int tid = threadIdx.x, lane = tid & 31, wid = tid >> 5;
    int b = blockIdx.y;
    int t = blockIdx.x;
    int i = 0;
    while (t >= 16 - i) { t -= 16 - i; i++; }
    int j = i + t;
    int ibase = i * 128, jbase = j * 128;

    const __half* xh = reinterpret_cast<const __half*>(g_buf + O_XH);
    const __half* xm = reinterpret_cast<const __half*>(g_buf + O_XM);

    {
        const __half* srcs[4] = { xh + ((size_t)b * NP + ibase) * CC,
                                  xm + ((size_t)b * NP + ibase) * CC,
                                  xh + ((size_t)b * NP + jbase) * CC,
                                  xm + ((size_t)b * NP + jbase) * CC };
        __half* dsts[4] = { As, As + 128, Bs, Bs + 128 };
#pragma unroll
        for (int s = 0; s < 4; s++) {
            const __half* src = srcs[s];
            __half* dst = dsts[s];
#pragma unroll
            for (int idx = tid; idx < 2048; idx += 256) {
                int row = idx >> 4, ch = idx & 15;
                *(uint4*)(dst + (size_t)row * LDA + ch * 8) =
                    *(const uint4*)(src + (size_t)row * CC + ch * 8);
            }
        }
    }
    if (tid < 128) xxi_s[tid] = g_buf[O_XX + b * NP + ibase + tid];
    else           xxj_s[tid - 128] = g_buf[O_XX + b * NP + jbase + (tid - 128)];
    __syncthreads();

    int mw = wid & 1, nw = wid >> 1;
    uint32_t a_s0 = smem_u32(As + (size_t)(mw * 64) * LDA);
    uint32_t b_s0 = smem_u32(Bs + (size_t)(nw * 32) * LDA);

    float acc[4][4][4];
#pragma unroll
    for (int a1 = 0; a1 < 4; a1++)
#pragma unroll
        for (int a2 = 0; a2 < 4; a2++)
#pragma unroll
            for (int a3 = 0; a3 < 4; a3++) acc[a1][a2][a3] = 0.f;

    int lrow = lane & 15, lcol8 = (lane >> 4) * 8;

#pragma unroll
    for (int k16 = 0; k16 < 8; k16++) {
        int kch = k16 * 16 + lcol8;
        uint32_t ah[4][4], am[4][4], bh[2][4], bm[2][4];
#pragma unroll
        for (int mi = 0; mi < 4; mi++) {
            uint32_t rb = a_s0 + (uint32_t)(((mi * 16 + lrow) * LDA) * 2);
            LDSM4(ah[mi], rb + kch * 2);
            LDSM4(am[mi], rb + (128 + kch) * 2);
        }
#pragma unroll
        for (int nh = 0; nh < 2; nh++) {
            uint32_t rb = b_s0 + (uint32_t)(((nh * 16 + lrow) * LDA) * 2);
            LDSM4(bh[nh], rb + kch * 2);
            LDSM4(bm[nh], rb + (128 + kch) * 2);
        }
#pragma unroll
        for (int mi = 0; mi < 4; mi++)
#pragma unroll
            for (int ni = 0; ni < 4; ni++) {
                uint32_t h0 = bh[ni >> 1][ni & 1], h1 = bh[ni >> 1][2 + (ni & 1)];
                uint32_t m0 = bm[ni >> 1][ni & 1], m1 = bm[ni >> 1][2 + (ni & 1)];
                MMA16816(acc[mi][ni], ah[mi], h0, h1);
                MMA16816(acc[mi][ni], ah[mi], m0, m1);
                MMA16816(acc[mi][ni], am[mi], h0, h1);
            }
    }

    int g = lane >> 2, q = lane & 3;
    float* pdb = g_buf + O_PD + (size_t)b * NP * NP;
#pragma unroll
    for (int mi = 0; mi < 4; mi++)
#pragma unroll
        for (int ni = 0; ni < 4; ni++) {
            int r0 = mw * 64 + mi * 16 + g;
            int c0 = nw * 32 + ni * 8 + q * 2;
            float xj0 = xxj_s[c0], xj1 = xxj_s[c0 + 1];
            float xi0 = xxi_s[r0], xi1 = xxi_s[r0 + 8];
            float2 v01, v23;
            v01.x = 2.f * acc[mi][ni][0] - xi0 - xj0;
            v01.y = 2.f * acc[mi][ni][1] - xi0 - xj1;
            v23.x = 2.f * acc[mi][ni][2] - xi1 - xj0;
            v23.y = 2.f * acc[mi][ni][3] - xi1 - xj1;
            *(float2*)(pdb + (size_t)(ibase + r0) * NP + jbase + c0) = v01;
            *(float2*)(pdb + (size_t)(ibase + r0 + 8) * NP + jbase + c0) = v23;
        }

    __syncthreads();
    if (ibase != jbase) {
        float* patch = (float*)(ps + 1024) + (size_t)wid * 32 * 68;
#pragma unroll
        for (int mi = 0; mi < 4; mi++)
#pragma unroll
            for (int ni = 0; ni < 4; ni++) {
                int rl = mi * 16 + g;
                int cl = ni * 8 + q * 2;
                int r0 = mw * 64 + rl, c0 = nw * 32 + cl;
                float xj0 = xxj_s[c0], xj1 = xxj_s[c0 + 1];
                float xi0 = xxi_s[r0], xi1 = xxi_s[r0 + 8];
                patch[(cl + 0) * 68 + rl]     = 2.f * acc[mi][ni][0] - xi0 - xj0;
                patch[(cl + 1) * 68 + rl]     = 2.f * acc[mi][ni][1] - xi0 - xj1;
                patch[(cl + 0) * 68 + rl + 8] = 2.f * acc[mi][ni][2] - xi1 - xj0;
                patch[(cl + 1) * 68 + rl + 8] = 2.f * acc[mi][ni][3] - xi1 - xj1;
            }
        __syncwarp();
#pragma unroll
        for (int cc = 0; cc < 32; cc++) {
            float2 val = *(float2*)(patch + cc * 68 + lane * 2);
            *(float2*)(pdb + (size_t)(jbase + nw * 32 + cc) * NP + ibase + mw * 64 + lane * 2) = val;
        }
    }
}

// ---------------- HMMA conv1x1 (shared-fragment mainloop) ----------------
// MODE 0=QKV (out fp32 [b][n][c])  2=W1-fused (K=256: x then av, out fp32 [b][o][n])
// 3=W2 (K=256, pre-split h2 input, residual, out fp32)
#define CLDA 264
#define CONV_SMEM (2 * 128 * CLDA * 2)

template<int MODE>
__global__ void __launch_bounds__(256, 1) conv_mma(const float* __restrict__ bias0,
                                                   const float* __restrict__ bias1,
                                                   const float* __restrict__ bias2,
                                                   const float* __restrict__ resid,
                                                   float* __restrict__ outp) {
    extern __shared__ char cs[];
    __half* As = (__half*)cs;
    __half* Bs = As + 128 * CLDA;
    int tid = threadIdx.x, lane = tid & 31, wid = tid >> 5;
    int b = blockIdx.z, nbase = blockIdx.x * 128;
    int yb = blockIdx.y;

    const __half* WH = reinterpret_cast<const __half*>(g_buf + O_WH);
    const __half* WM = reinterpret_cast<const __half*>(g_buf + O_WM2);
    int woff, wstride, obase = 0;
    if (MODE == 0)      { woff = yb * 16384; wstride = 128; }
    else if (MODE == 2) { woff = WOFF_1 + yb * 128 * 256; wstride = 256; obase = yb * 128; }
    else                { woff = WOFF_2; wstride = 256; }
    const int KCH = (MODE >= 2) ? 2 : 1;

    float acc[4][4][4];
#pragma unroll
    for (int a1 = 0; a1 < 4; a1++)
#pragma unroll
        for (int a2 = 0; a2 < 4; a2++)
#pragma unroll
            for (int a3 = 0; a3 < 4; a3++) acc[a1][a2][a3] = 0.f;

    int mw = wid & 1, nw = wid >> 1;
    int lrow = lane & 15, lcol8 = (lane >> 4) * 8;
    uint32_t a_s0 = smem_u32(As + (size_t)(mw * 64) * CLDA);
    uint32_t b_s0 = smem_u32(Bs + (size_t)(nw * 32) * CLDA);

#pragma unroll
    for (int kc = 0; kc < KCH; kc++) {
        const __half* wsh = WH + woff + kc * 128;
        const __half* wsm = WM + woff + kc * 128;
#pragma unroll
        for (int idx = tid; idx < 2048; idx += 256) {
            int row = idx >> 4, ch = idx & 15;
            *(uint4*)(As + (size_t)row * CLDA + ch * 8) =
                *(const uint4*)(wsh + (size_t)row * wstride + ch * 8);
            *(uint4*)(As + (size_t)row * CLDA + 128 + ch * 8) =
                *(const uint4*)(wsm + (size_t)row * wstride + ch * 8);
        }
        const __half *bh, *bm; int bstr;
        if (MODE == 0) { bh = (const __half*)(g_buf + O_XH); bm = (const __half*)(g_buf + O_XM); bstr = 128; }
        else if (MODE == 2) {
            if (kc == 0) { bh = (const __half*)(g_buf + O_XH); bm = (const __half*)(g_buf + O_XM); }
            else         { bh = (const __half*)(g_buf + O_AVH); bm = (const __half*)(g_buf + O_AVM); }
            bstr = 128;
        } else {
            bh = (const __half*)(g_buf + O_H2H) + kc * 128;
            bm = (const __half*)(g_buf + O_H2M) + kc * 128;
            bstr = 256;
        }
        const __half* bhp = bh + (size_t)(b * NP + nbase) * bstr;
        const __half* bmp = bm + (size_t)(b * NP + nbase) * bstr;
#pragma unroll
        for (int idx = tid; idx < 2048; idx += 256) {
            int row = idx >> 4, ch = idx & 15;
            *(uint4*)(Bs + (size_t)row * CLDA + ch * 8) =
                *(const uint4*)(bhp + (size_t)row * bstr + ch * 8);
            *(uint4*)(Bs + (size_t)row * CLDA + 128 + ch * 8) =
                *(const uint4*)(bmp + (size_t)row * bstr + ch * 8);
        }
        __syncthreads();

#pragma unroll
        for (int k16 = 0; k16 < 8; k16++) {
            int kch = k16 * 16 + lcol8;
            uint32_t ah[4][4], am[4][4], bhf[2][4], bmf[2][4];
#pragma unroll
            for (int mi = 0; mi < 4; mi++) {
                uint32_t rb = a_s0 + (uint32_t)(((mi * 16 + lrow) * CLDA) * 2);
                LDSM4(ah[mi], rb + kch * 2);
                LDSM4(am[mi], rb + (128 + kch) * 2);
            }
#pragma unroll
            for (int nh = 0; nh < 2; nh++) {
                uint32_t rb = b_s0 + (uint32_t)(((nh * 16 + lrow) * CLDA) * 2);
                LDSM4(bhf[nh], rb + kch * 2);
                LDSM4(bmf[nh], rb + (128 + kch) * 2);
            }
#pragma unroll
            for (int mi = 0; mi < 4; mi++)
#pragma unroll
                for (int ni = 0; ni < 4; ni++) {
                    uint32_t h0 = bhf[ni >> 1][ni & 1], h1 = bhf[ni >> 1][2 + (ni & 1)];
                    uint32_t m0 = bmf[ni >> 1][ni & 1], m1 = bmf[ni >> 1][2 + (ni & 1)];
                    MMA16816(acc[mi][ni], ah[mi], h0, h1);
                    MMA16816(acc[mi][ni], ah[mi], m0, m1);
                    MMA16816(acc[mi][ni], am[mi], h0, h1);
                }
        }
        __syncthreads();
    }

    int g = lane >> 2, q = lane & 3;
    if (MODE == 0) {
        const float* bias_ = (yb == 0 ? bias0 : yb == 1 ? bias1 : bias2);
        float* patch = (float*)cs + (size_t)wid * 32 * 68;
#pragma unroll
        for (int mi = 0; mi < 4; mi++)
#pragma unroll
            for (int ni = 0; ni < 4; ni++) {
                int rl = mi * 16 + g;
                int cl = ni * 8 + q * 2;
                float bs0 = bias_[mw * 64 + rl], bs1 = bias_[mw * 64 + rl + 8];
                patch[(cl + 0) * 68 + rl]     = acc[mi][ni][0] + bs0;
                patch[(cl + 1) * 68 + rl]     = acc[mi][ni][1] + bs0;
                patch[(cl + 0) * 68 + rl + 8] = acc[mi][ni][2] + bs1;
                patch[(cl + 1) * 68 + rl + 8] = acc[mi][ni][3] + bs1;
            }
        __syncwarp();
        float* Y = g_buf + O_QT + (size_t)yb * BB * NP * CC;
#pragma unroll
        for (int r = 0; r < 32; r++) {
            int n = nbase + nw * 32 + r;
            *(float2*)(Y + ((size_t)b * NP + n) * CC + mw * 64 + lane * 2) =
                *(float2*)(patch + r * 68 + lane * 2);
        }
    } else {
        const float* bias_ = bias0;
        float* Yb = outp + (size_t)b * ((MODE == 2) ? C2 * NP : CC * NP);
#pragma unroll
        for (int mi = 0; mi < 4; mi++)
#pragma unroll
            for (int ni = 0; ni < 4; ni++) {
                int r0 = obase + mw * 64 + mi * 16 + g;
                int c0 = nbase + nw * 32 + ni * 8 + q * 2;
                float bs0 = bias_[r0], bs1 = bias_[r0 + 8];
                float2 v01, v23;
                v01.x = acc[mi][ni][0] + bs0; v01.y = acc[mi][ni][1] + bs0;
                v23.x = acc[mi][ni][2] + bs1; v23.y = acc[mi][ni][3] + bs1;
                if (MODE == 3) {
                    const float* rb = resid + (size_t)b * CC * NP;
                    v01.x += rb[(size_t)r0 * NP + c0];
                    v01.y += rb[(size_t)r0 * NP + c0 + 1];
                    v23.x += rb[(size_t)(r0 + 8) * NP + c0];
                    v23.y += rb[(size_t)(r0 + 8) * NP + c0 + 1];
                }
                *(float2*)(Yb + (size_t)r0 * NP + c0) = v01;
                *(float2*)(Yb + (size_t)(r0 + 8) * NP + c0) = v23;
            }
    }
}

// ---------------- warp-per-row top-20 ----------------
#define TOPK_SMEM (8 * 2048 * 4)
__global__ void __launch_bounds__(256) topk_kernel() {
    extern __shared__ float srows[];
    const unsigned FULL = 0xffffffffu;
    int tid = threadIdx.x, lane = tid & 31, wid = tid >> 5;
    int rowbase = blockIdx.x * 8;
    const float4* g4 = (const float4*)(g_buf + O_PD + (size_t)rowbase * NP);
    float4* s4 = (float4*)srows;
#pragma unroll
    for (int i = tid; i < 8 * 512; i += 256) s4[i] = g4[i];
    __syncthreads();

    float* s = srows + wid * 2048 + lane * 64;
    float bv = -3.4e38f; int bi = 0;
#pragma unroll
    for (int k4 = 0; k4 < 16; k4++) {
        float4 vv = *(float4*)(s + k4 * 4);
        if (vv.x > bv) { bv = vv.x; bi = k4 * 4 + 0; }
        if (vv.y > bv) { bv = vv.y; bi = k4 * 4 + 1; }
        if (vv.z > bv) { bv = vv.z; bi = k4 * 4 + 2; }
        if (vv.w > bv) { bv = vv.w; bi = k4 * 4 + 3; }
    }
    int gbase = lane * 64;
    int* idxout = reinterpret_cast<int*>(g_buf + O_IDX) + (size_t)(rowbase + wid) * KNN;

    for (int it = 0; it < KNN; it++) {
        float cv = bv; int ci = gbase + bi;
#pragma unroll
        for (int off = 16; off; off >>= 1) {
            float ov = __shfl_down_sync(FULL, cv, off);
            int oi = __shfl_down_sync(FULL, ci, off);
            if (ov > cv || (ov == cv && oi < ci)) { cv = ov; ci = oi; }
        }
        ci = __shfl_sync(FULL, ci, 0);
        if (lane == 0) idxout[it] = ci;
        if ((ci >> 6) == lane) {
            s[ci & 63] = -3.4e38f;
            bv = -3.4e38f; bi = 0;
#pragma unroll
            for (int k4 = 0; k4 < 16; k4++) {
                float4 vv = *(float4*)(s + k4 * 4);
                if (vv.x > bv) { bv = vv.x; bi = k4 * 4 + 0; }
                if (vv.y > bv) { bv = vv.y; bi = k4 * 4 + 1; }
                if (vv.z > bv) { bv = vv.z; bi = k4 * 4 + 2; }
                if (vv.w > bv) { bv = vv.w; bi = k4 * 4 + 3; }
            }
        }
    }
}

// ---------------- sparse mutual-kNN attention: one warp per (b,n) ----------------
__global__ void attn_kernel() {
    const unsigned FULL = 0xffffffffu;
    int gwarp = (blockIdx.x * blockDim.x + threadIdx.x) >> 5;
    int lane = threadIdx.x & 31;
    int b = gwarp / NP, n = gwarp - b * NP;

    const float* qT = g_buf + O_QT;
    const float* kT = g_buf + O_QT + BB * NP * CC;
    const float* vT = g_buf + O_QT + 2 * BB * NP * CC;
    const int* idx = reinterpret_cast<const int*>(g_buf + O_IDX);

    const float* qrow = qT + ((size_t)b * NP + n) * CC;
    float q0 = qrow[lane], q1 = qrow[lane + 32], q2 = qrow[lane + 64], q3 = qrow[lane + 96];

    int mj = 0, act = 0;
    if (lane < KNN) {
        mj = idx[(b * NP + n) * KNN + lane];
        const int* lst = idx + (size_t)(b * NP + mj) * KNN;
#pragma unroll
        for (int tt = 0; tt < KNN; tt++) act |= (lst[tt] == n);
    }
    unsigned amask = __ballot_sync(FULL, act);

    float sc[4] = {0.f, 0.f, 0.f, 0.f};
    for (int jj = 0; jj < KNN; jj++) {
        if (!((amask >> jj) & 1)) continue;
        int m = __shfl_sync(FULL, mj, jj);
        const float* krow = kT + ((size_t)b * NP + m) * CC;
        float p0 = q0 * krow[lane], p1 = q1 * krow[lane + 32];
        float p2 = q2 * krow[lane + 64], p3 = q3 * krow[lane + 96];
#pragma unroll
        for (int off = 16; off; off >>= 1) {
            p0 += __shfl_xor_sync(FULL, p0, off);
            p1 += __shfl_xor_sync(FULL, p1, off);
            p2 += __shfl_xor_sync(FULL, p2, off);
            p3 += __shfl_xor_sync(FULL, p3, off);
        }
        if (lane == jj) { sc[0] = p0; sc[1] = p1; sc[2] = p2; sc[3] = p3; }
    }

    const float scale = 0.17677669529663687f;
    bool live = (lane < KNN) && ((amask >> lane) & 1);
    float p[4];
#pragma unroll
    for (int hh = 0; hh < 4; hh++) {
        float v = live ? sc[hh] * scale : -3.4e38f;
        float mx = v;
#pragma unroll
        for (int off = 16; off; off >>= 1) mx = fmaxf(mx, __shfl_xor_sync(FULL, mx, off));
        float e = live ? expf(v - mx) : 0.f;
        float sm = e;
#pragma unroll
        for (int off = 16; off; off >>= 1) sm += __shfl_xor_sync(FULL, sm, off);
        p[hh] = e / sm;
    }

    float a0 = 0.f, a1 = 0.f, a2 = 0.f, a3 = 0.f;
    for (int jj = 0; jj < KNN; jj++) {
        if (!((amask >> jj) & 1)) continue;
        int m = __shfl_sync(FULL, mj, jj);
        float w0 = __shfl_sync(FULL, p[0], jj);
        float w1 = __shfl_sync(FULL, p[1], jj);
        float w2 = __shfl_sync(FULL, p[2], jj);
        float w3 = __shfl_sync(FULL, p[3], jj);
        const float* vrow = vT + ((size_t)b * NP + m) * CC;
        a0 = fmaf(w0, vrow[lane], a0);
        a1 = fmaf(w1, vrow[lane + 32], a1);
        a2 = fmaf(w2, vrow[lane + 64], a2);
        a3 = fmaf(w3, vrow[lane + 96], a3);
    }
    __half* avh = (__half*)(g_buf + O_AVH);
    __half* avm = (__half*)(g_buf + O_AVM);
    size_t o = ((size_t)b * NP + n) * CC;
    float vals[4] = {a0, a1, a2, a3};
#pragma unroll
    for (int c = 0; c < 4; c++) {
        __half hh = __float2half_rn(vals[c]);
        avh[o + c * 32 + lane] = hh;
        avm[o + c * 32 + lane] = __float2half_rn(vals[c] - __half2float(hh));
    }
}

// ---------------- batchnorm statistics ----------------
__global__ void bn_stats_kernel() {
    __shared__ float ss[256], ss2[256];
    int c = blockIdx.x, tid = threadIdx.x;
    float s = 0.f, s2 = 0.f;
    for (int bn = tid; bn < BB * NP; bn += 256) {
        int b = bn >> 11, n = bn & (NP - 1);
        float v = g_buf[O_H + (size_t)b * C2 * NP + (size_t)c * NP + n];
        s += v; s2 = fmaf(v, v, s2);
    }
    ss[tid] = s; ss2[tid] = s2;
    __syncthreads();
    for (int off = 128; off; off >>= 1) {
        if (tid < off) { ss[tid] += ss[tid + off]; ss2[tid] += ss2[tid + off]; }
        __syncthreads();
    }
    if (tid == 0) {
        float inv = 1.f / (BB * NP);
        float mu = ss[0] * inv;
        float var = ss2[0] * inv - mu * mu;
        g_buf[O_MU + c] = mu;
        g_buf[O_ISTD + c] = rsqrtf(var + 1e-5f);
    }
}

// ---------------- bn+relu + transpose + split ----------------
__global__ void bnrelu_kernel(const float* __restrict__ gamma, const float* __restrict__ beta) {
    __shared__ float t[32][33];
    int b = blockIdx.z, cbase = blockIdx.y * 32, nbase = blockIdx.x * 32;
    int tid = threadIdx.x;
    const float* hsrc = g_buf + O_H + (size_t)b * C2 * NP;
#pragma unroll
    for (int i = tid; i < 1024; i += 256) {
        int c = i >> 5, n = i & 31;
        t[c][n] = hsrc[(size_t)(cbase + c) * NP + nbase + n];
    }
    __syncthreads();
    __half* h2h = (__half*)(g_buf + O_H2H);
    __half* h2m = (__half*)(g_buf + O_H2M);
#pragma unroll
    for (int i = tid; i < 1024; i += 256) {
        int n = i >> 5, c = i & 31;
        int cg = cbase + c;
        float v = t[c][n];
        v = fmaxf(fmaf((v - g_buf[O_MU + cg]) * g_buf[O_ISTD + cg], gamma[cg], beta[cg]), 0.f);
        __half hh = __float2half_rn(v);
        size_t o = ((size_t)b * NP + nbase + n) * C2 + cg;
        h2h[o] = hh;
        h2m[o] = __float2half_rn(v - __half2float(hh));
    }
}

// ---------------- launch ----------------
extern "C" void kernel_launch(void* const* d_in, const int* in_sizes, int n_in,
                              void* d_out, int out_size) {
    (void)in_sizes; (void)n_in; (void)out_size;
    const float* x     = (const float*)d_in[0];
    const float* wq    = (const float*)d_in[1];
    const float* bq    = (const float*)d_in[2];
    const float* wk    = (const float*)d_in[3];
    const float* bk    = (const float*)d_in[4];
    const float* wv    = (const float*)d_in[5];
    const float* bv    = (const float*)d_in[6];
    const float* wm    = (const float*)d_in[7];
    const float* bm    = (const float*)d_in[8];
    const float* w1    = (const float*)d_in[9];
    const float* b1    = (const float*)d_in[10];
    const float* gamma = (const float*)d_in[11];
    const float* beta  = (const float*)d_in[12];
    const float* w2    = (const float*)d_in[13];
    const float* b2    = (const float*)d_in[14];
    float* out = (float*)d_out;

    float* base = nullptr;
    cudaGetSymbolAddress((void**)&base, g_buf);
    float* p_h = base + O_H;
    float* p_b1p = base + O_B1P;

    static cudaStream_t s2 = nullptr, s3 = nullptr;
    static cudaEvent_t evFork = nullptr, evPrep = nullptr, evXX = nullptr,
                       evQKV = nullptr, evW = nullptr;
    if (s2 == nullptr) {
        cudaStreamCreateWithFlags(&s2, cudaStreamNonBlocking);
        cudaStreamCreateWithFlags(&s3, cudaStreamNonBlocking);
        cudaEventCreateWithFlags(&evFork, cudaEventDisableTiming);
        cudaEventCreateWithFlags(&evPrep, cudaEventDisableTiming);
        cudaEventCreateWithFlags(&evXX, cudaEventDisableTiming);
        cudaEventCreateWithFlags(&evQKV, cudaEventDisableTiming);
        cudaEventCreateWithFlags(&evW, cudaEventDisableTiming);
    }

    cudaFuncSetAttribute(pd_mma_kernel, cudaFuncAttributeMaxDynamicSharedMemorySize, PD_SMEM);
    cudaFuncSetAttribute(conv_mma<0>, cudaFuncAttributeMaxDynamicSharedMemorySize, CONV_SMEM);
    cudaFuncSetAttribute(conv_mma<2>, cudaFuncAttributeMaxDynamicSharedMemorySize, CONV_SMEM);
    cudaFuncSetAttribute(conv_mma<3>, cudaFuncAttributeMaxDynamicSharedMemorySize, CONV_SMEM);
    cudaFuncSetAttribute(topk_kernel, cudaFuncAttributeMaxDynamicSharedMemorySize, TOPK_SMEM);

    // fork point
    cudaEventRecord(evFork, 0);
    cudaStreamWaitEvent(s2, evFork, 0);
    cudaStreamWaitEvent(s3, evFork, 0);

    // s2: weight split -> (wait prep) qkv conv -> weight fuse
    wsplit_kernel<<<(WTOT + 255) / 256, 256, 0, s2>>>(wq, wk, wv, wm, w1, w2);
    // s3: xx
    xx_kernel<<<(BB * NP + 255) / 256, 256, 0, s3>>>(x);
    cudaEventRecord(evXX, s3);
    // main: prep
    prep_kernel<<<dim3(NP / 64, CC / 32, BB), 256>>>(x);
    cudaEventRecord(evPrep, 0);

    cudaStreamWaitEvent(s2, evPrep, 0);
    conv_mma<0><<<dim3(NP / 128, 3, BB), 256, CONV_SMEM, s2>>>(bq, bk, bv, nullptr, nullptr);
    cudaEventRecord(evQKV, s2);
    wfuse_kernel<<<256, 128, 0, s2>>>(w1, wm, bm, b1);
    cudaEventRecord(evW, s2);

    // main: pd -> topk (needs prep + xx)
    cudaStreamWaitEvent(0, evXX, 0);
    pd_mma_kernel<<<dim3(136, BB), 256, PD_SMEM>>>();
    topk_kernel<<<BB * NP / 8, 256, TOPK_SMEM>>>();

    cudaStreamWaitEvent(0, evQKV, 0);
    attn_kernel<<<BB * NP / 8, 256>>>();

    cudaStreamWaitEvent(0, evW, 0);
    conv_mma<2><<<dim3(NP / 128, 2, BB), 256, CONV_SMEM>>>(p_b1p, nullptr, nullptr, nullptr, p_h);

    bn_stats_kernel<<<C2, 256>>>();
    bnrelu_kernel<<<dim3(NP / 32, C2 / 32, BB), 256>>>(gamma, beta);

    conv_mma<3><<<dim3(NP / 128, 1, BB), 256, CONV_SMEM>>>(b2, nullptr, nullptr, x, out);
}

// round 15
// speedup vs baseline: 1.2332x; 1.1166x over previous
#include <cuda_runtime.h>
#include <cuda_fp16.h>
#include <math.h>
#include <stdint.h>

#define BB 2
#define CC 128
#define NP 2048
#define KNN 20
#define C2 256

// packed weight-split offsets (halfs)
#define WOFF_Q 0
#define WOFF_K 16384
#define WOFF_V 32768
#define WOFF_M 49152
#define WOFF_1 65536
#define WOFF_2 131072
#define WTOT   163840

// ---------------- scratch arena (floats) ----------------
#define O_QT   0                               // 3 * B*N*C fp32 (q,k,v transposed [b][n][c])
#define O_XX   (O_QT + 3*BB*NP*CC)
#define O_H    (O_XX + BB*NP)                  // B*2C*N fp32 (w1 out, [b][c][n])
#define O_MU   (O_H + BB*C2*NP)
#define O_ISTD (O_MU + C2)
#define O_B1P  (O_ISTD + C2)                   // fused bias b1' (256)
#define O_IDX  (O_B1P + C2)                    // B*N*KNN ints
#define O_XH   (O_IDX + BB*NP*KNN)             // halfs [b][n][c]
#define O_XM   (O_XH + BB*NP*CC/2)
#define O_AVH  (O_XM + BB*NP*CC/2)
#define O_AVM  (O_AVH + BB*NP*CC/2)
#define O_H2H  (O_AVM + BB*NP*CC/2)            // halfs [b][n][2C]
#define O_H2M  (O_H2H + BB*NP*C2/2)
#define O_WH   (O_H2M + BB*NP*C2/2)            // packed weight halves
#define O_WM2  (O_WH + WTOT/2)
#define O_PD   (O_WM2 + WTOT/2)
#define TOTALF (O_PD + (size_t)BB*NP*NP)

__device__ __align__(16) float g_buf[TOTALF];

__device__ __forceinline__ uint32_t smem_u32(const void* p) {
    uint32_t a;
    asm("{ .reg .u64 t; cvta.to.shared.u64 t, %1; cvt.u32.u64 %0, t; }" : "=r"(a) : "l"(p));
    return a;
}

#define LDSM4(r, addr) \
    asm volatile("ldmatrix.sync.aligned.m8n8.x4.shared.b16 {%0,%1,%2,%3}, [%4];" \
                 : "=r"((r)[0]), "=r"((r)[1]), "=r"((r)[2]), "=r"((r)[3]) : "r"(addr))

#define MMA16816(acc, a, b0, b1) \
    asm volatile("mma.sync.aligned.m16n8k16.row.col.f32.f16.f16.f32 " \
                 "{%0,%1,%2,%3}, {%4,%5,%6,%7}, {%8,%9}, {%0,%1,%2,%3};" \
                 : "+f"((acc)[0]), "+f"((acc)[1]), "+f"((acc)[2]), "+f"((acc)[3]) \
                 : "r"((a)[0]), "r"((a)[1]), "r"((a)[2]), "r"((a)[3]), "r"(b0), "r"(b1))

// ---------------- xx[b][n] = sum_c x^2 ----------------
__global__ void xx_kernel(const float* __restrict__ x) {
    int i = blockIdx.x * blockDim.x + threadIdx.x;
    if (i >= BB * NP) return;
    int b = i / NP, n = i - b * NP;
    const float* xb = x + (size_t)b * CC * NP + n;
    float s = 0.f;
#pragma unroll 8
    for (int c = 0; c < CC; c++) { float v = xb[(size_t)c * NP]; s = fmaf(v, v, s); }
    g_buf[O_XX + i] = s;
}

// ---------------- transpose + 2-way fp16 split: xT_{h,m}[b][n][c] ----------------
__global__ void prep_kernel(const float* __restrict__ x) {
    __shared__ float ts[32][65];
    int b = blockIdx.z;
    int cbase = blockIdx.y * 32, nbase = blockIdx.x * 64;
    int tid = threadIdx.x;
    __half* xh = reinterpret_cast<__half*>(g_buf + O_XH);
    __half* xm = reinterpret_cast<__half*>(g_buf + O_XM);
#pragma unroll
    for (int i = 0; i < 8; i++) {
        int idx = tid + i * 256;
        int cr = idx >> 6, nn = idx & 63;
        ts[cr][nn] = x[(size_t)b * CC * NP + (size_t)(cbase + cr) * NP + nbase + nn];
    }
    __syncthreads();
#pragma unroll
    for (int i = 0; i < 8; i++) {
        int idx = tid + i * 256;
        int nr = idx >> 5, cc = idx & 31;
        float v = ts[cc][nr];
        __half h1 = __float2half_rn(v);
        __half h2 = __float2half_rn(v - __half2float(h1));
        size_t o = ((size_t)b * NP + nbase + nr) * CC + cbase + cc;
        xh[o] = h1; xm[o] = h2;
    }
}

// ---------------- split all weights to fp16 h/m ----------------
__global__ void wsplit_kernel(const float* __restrict__ wq, const float* __restrict__ wk,
                              const float* __restrict__ wv, const float* __restrict__ wmp,
                              const float* __restrict__ w1, const float* __restrict__ w2) {
    int i = blockIdx.x * 256 + threadIdx.x;
    if (i >= WTOT) return;
    float v;
    if (i < 16384) v = wq[i];
    else if (i < 32768) v = wk[i - 16384];
    else if (i < 49152) v = wv[i - 32768];
    else if (i < 65536) v = wmp[i - 49152];
    else if (i < 131072) v = w1[i - 65536];
    else v = w2[i - 131072];
    __half h = __float2half_rn(v);
    reinterpret_cast<__half*>(g_buf + O_WH)[i] = h;
    reinterpret_cast<__half*>(g_buf + O_WM2)[i] = __float2half_rn(v - __half2float(h));
}

// ---------------- fold wm into w1: F = w1[:,128:]@wm, b1' = b1 + w1[:,128:]@bm ----------------
__global__ void wfuse_kernel(const float* __restrict__ w1, const float* __restrict__ wm,
                             const float* __restrict__ bm, const float* __restrict__ b1) {
    int o = blockIdx.x;            // 0..255
    int c = threadIdx.x;           // 0..127
    float s = 0.f;
#pragma unroll 8
    for (int k = 0; k < 128; k++)
        s = fmaf(w1[o * 256 + 128 + k], wm[k * 128 + c], s);
    __half h = __float2half_rn(s);
    int i = WOFF_1 + o * 256 + 128 + c;
    reinterpret_cast<__half*>(g_buf + O_WH)[i] = h;
    reinterpret_cast<__half*>(g_buf + O_WM2)[i] = __float2half_rn(s - __half2float(h));
    if (c == 0) {
        float bsum = b1[o];
        for (int k = 0; k < 128; k++) bsum = fmaf(w1[o * 256 + 128 + k], bm[k], bsum);
        g_buf[O_B1P + o] = bsum;
    }
}

// ---------------- pd via mma.sync HMMA: D ~ hh + hm + mh (shared fragments) ----------------
#define LDA 264
#define PD_SMEM (1024 + 2 * 128 * LDA * 2)

__global__ void __launch_bounds__(256, 1) pd_mma_kernel() {
    extern __shared__ char ps[];
    float* xxi_s = (float*)ps;
    float* xxj_s = (float*)(ps + 512);
    __half* As = (__half*)(ps + 1024);
    __half* Bs = As + 128 * LDA;

    int tid = threadIdx.x, lane = tid & 31, wid = tid >> 5;
    int b = blockIdx.y;
    int t = blockIdx.x;
    int i = 0;
    while (t >= 16 - i) { t -= 16 - i; i++; }
    int j = i + t;
    int ibase = i * 128, jbase = j * 128;

    const __half* xh = reinterpret_cast<const __half*>(g_buf + O_XH);
    const __half* xm = reinterpret_cast<const __half*>(g_buf + O_XM);

    {
        const __half* srcs[4] = { xh + ((size_t)b * NP + ibase) * CC,
                                  xm + ((size_t)b * NP + ibase) * CC,
                                  xh + ((size_t)b * NP + jbase) * CC,
                                  xm + ((size_t)b * NP + jbase) * CC };
        __half* dsts[4] = { As, As + 128, Bs, Bs + 128 };
#pragma unroll
        for (int s = 0; s < 4; s++) {
            const __half* src = srcs[s];
            __half* dst = dsts[s];
#pragma unroll
            for (int idx = tid; idx < 2048; idx += 256) {
                int row = idx >> 4, ch = idx & 15;
                *(uint4*)(dst + (size_t)row * LDA + ch * 8) =
                    *(const uint4*)(src + (size_t)row * CC + ch * 8);
            }
        }
    }
    if (tid < 128) xxi_s[tid] = g_buf[O_XX + b * NP + ibase + tid];
    else           xxj_s[tid - 128] = g_buf[O_XX + b * NP + jbase + (tid - 128)];
    __syncthreads();

    int mw = wid & 1, nw = wid >> 1;
    uint32_t a_s0 = smem_u32(As + (size_t)(mw * 64) * LDA);
    uint32_t b_s0 = smem_u32(Bs + (size_t)(nw * 32) * LDA);

    float acc[4][4][4];
#pragma unroll
    for (int a1 = 0; a1 < 4; a1++)
#pragma unroll
        for (int a2 = 0; a2 < 4; a2++)
#pragma unroll
            for (int a3 = 0; a3 < 4; a3++) acc[a1][a2][a3] = 0.f;

    int lrow = lane & 15, lcol8 = (lane >> 4) * 8;

#pragma unroll
    for (int k16 = 0; k16 < 8; k16++) {
        int kch = k16 * 16 + lcol8;
        uint32_t ah[4][4], am[4][4], bh[2][4], bm[2][4];
#pragma unroll
        for (int mi = 0; mi < 4; mi++) {
            uint32_t rb = a_s0 + (uint32_t)(((mi * 16 + lrow) * LDA) * 2);
            LDSM4(ah[mi], rb + kch * 2);
            LDSM4(am[mi], rb + (128 + kch) * 2);
        }
#pragma unroll
        for (int nh = 0; nh < 2; nh++) {
            uint32_t rb = b_s0 + (uint32_t)(((nh * 16 + lrow) * LDA) * 2);
            LDSM4(bh[nh], rb + kch * 2);
            LDSM4(bm[nh], rb + (128 + kch) * 2);
        }
#pragma unroll
        for (int mi = 0; mi < 4; mi++)
#pragma unroll
            for (int ni = 0; ni < 4; ni++) {
                uint32_t h0 = bh[ni >> 1][ni & 1], h1 = bh[ni >> 1][2 + (ni & 1)];
                uint32_t m0 = bm[ni >> 1][ni & 1], m1 = bm[ni >> 1][2 + (ni & 1)];
                MMA16816(acc[mi][ni], ah[mi], h0, h1);
                MMA16816(acc[mi][ni], ah[mi], m0, m1);
                MMA16816(acc[mi][ni], am[mi], h0, h1);
            }
    }

    int g = lane >> 2, q = lane & 3;
    float* pdb = g_buf + O_PD + (size_t)b * NP * NP;
#pragma unroll
    for (int mi = 0; mi < 4; mi++)
#pragma unroll
        for (int ni = 0; ni < 4; ni++) {
            int r0 = mw * 64 + mi * 16 + g;
            int c0 = nw * 32 + ni * 8 + q * 2;
            float xj0 = xxj_s[c0], xj1 = xxj_s[c0 + 1];
            float xi0 = xxi_s[r0], xi1 = xxi_s[r0 + 8];
            float2 v01, v23;
            v01.x = 2.f * acc[mi][ni][0] - xi0 - xj0;
            v01.y = 2.f * acc[mi][ni][1] - xi0 - xj1;
            v23.x = 2.f * acc[mi][ni][2] - xi1 - xj0;
            v23.y = 2.f * acc[mi][ni][3] - xi1 - xj1;
            *(float2*)(pdb + (size_t)(ibase + r0) * NP + jbase + c0) = v01;
            *(float2*)(pdb + (size_t)(ibase + r0 + 8) * NP + jbase + c0) = v23;
        }

    __syncthreads();
    if (ibase != jbase) {
        float* patch = (float*)(ps + 1024) + (size_t)wid * 32 * 68;
#pragma unroll
        for (int mi = 0; mi < 4; mi++)
#pragma unroll
            for (int ni = 0; ni < 4; ni++) {
                int rl = mi * 16 + g;
                int cl = ni * 8 + q * 2;
                int r0 = mw * 64 + rl, c0 = nw * 32 + cl;
                float xj0 = xxj_s[c0], xj1 = xxj_s[c0 + 1];
                float xi0 = xxi_s[r0], xi1 = xxi_s[r0 + 8];
                patch[(cl + 0) * 68 + rl]     = 2.f * acc[mi][ni][0] - xi0 - xj0;
                patch[(cl + 1) * 68 + rl]     = 2.f * acc[mi][ni][1] - xi0 - xj1;
                patch[(cl + 0) * 68 + rl + 8] = 2.f * acc[mi][ni][2] - xi1 - xj0;
                patch[(cl + 1) * 68 + rl + 8] = 2.f * acc[mi][ni][3] - xi1 - xj1;
            }
        __syncwarp();
#pragma unroll
        for (int cc = 0; cc < 32; cc++) {
            float2 val = *(float2*)(patch + cc * 68 + lane * 2);
            *(float2*)(pdb + (size_t)(jbase + nw * 32 + cc) * NP + ibase + mw * 64 + lane * 2) = val;
        }
    }
}

// ---------------- HMMA conv1x1 (shared-fragment mainloop) ----------------
// MODE 0=QKV (NT=128, out fp32 [b][n][c])
// MODE 2=W1-fused (NT=64, K=256: x then av, out fp32 [b][o][n])
// MODE 3=W2 (NT=64, K=256, pre-split h2 input, residual, out fp32)
#define CLDA 264
#define CONV_SMEM0  (2 * 128 * CLDA * 2)
#define CONV_SMEM64 ((128 + 64) * CLDA * 2)

template<int MODE>
__global__ void __launch_bounds__(256, 1) conv_mma(const float* __restrict__ bias0,
                                                   const float* __restrict__ bias1,
                                                   const float* __restrict__ bias2,
                                                   const float* __restrict__ resid,
                                                   float* __restrict__ outp) {
    constexpr int NT = (MODE == 0) ? 128 : 64;
    extern __shared__ char cs[];
    __half* As = (__half*)cs;
    __half* Bs = As + 128 * CLDA;
    int tid = threadIdx.x, lane = tid & 31, wid = tid >> 5;
    int b = blockIdx.z, nbase = blockIdx.x * NT;
    int yb = blockIdx.y;

    const __half* WH = reinterpret_cast<const __half*>(g_buf + O_WH);
    const __half* WM = reinterpret_cast<const __half*>(g_buf + O_WM2);
    int woff, wstride, obase = 0;
    if (MODE == 0)      { woff = yb * 16384; wstride = 128; }
    else if (MODE == 2) { woff = WOFF_1 + yb * 128 * 256; wstride = 256; obase = yb * 128; }
    else                { woff = WOFF_2; wstride = 256; }
    const int KCH = (MODE >= 2) ? 2 : 1;
    constexpr int NI = (NT == 128) ? 4 : 2;

    float acc[4][NI][4];
#pragma unroll
    for (int a1 = 0; a1 < 4; a1++)
#pragma unroll
        for (int a2 = 0; a2 < NI; a2++)
#pragma unroll
            for (int a3 = 0; a3 < 4; a3++) acc[a1][a2][a3] = 0.f;

    int mw = wid & 1, nw = wid >> 1;
    int lrow = lane & 15, lcol8 = (lane >> 4) * 8;
    uint32_t a_s0 = smem_u32(As + (size_t)(mw * 64) * CLDA);
    uint32_t b_s0 = smem_u32(Bs + (size_t)(nw * (NT / 4)) * CLDA);

#pragma unroll
    for (int kc = 0; kc < KCH; kc++) {
        const __half* wsh = WH + woff + kc * 128;
        const __half* wsm = WM + woff + kc * 128;
#pragma unroll
        for (int idx = tid; idx < 2048; idx += 256) {
            int row = idx >> 4, ch = idx & 15;
            *(uint4*)(As + (size_t)row * CLDA + ch * 8) =
                *(const uint4*)(wsh + (size_t)row * wstride + ch * 8);
            *(uint4*)(As + (size_t)row * CLDA + 128 + ch * 8) =
                *(const uint4*)(wsm + (size_t)row * wstride + ch * 8);
        }
        const __half *bh, *bm; int bstr;
        if (MODE == 0) { bh = (const __half*)(g_buf + O_XH); bm = (const __half*)(g_buf + O_XM); bstr = 128; }
        else if (MODE == 2) {
            if (kc == 0) { bh = (const __half*)(g_buf + O_XH); bm = (const __half*)(g_buf + O_XM); }
            else         { bh = (const __half*)(g_buf + O_AVH); bm = (const __half*)(g_buf + O_AVM); }
            bstr = 128;
        } else {
            bh = (const __half*)(g_buf + O_H2H) + kc * 128;
            bm = (const __half*)(g_buf + O_H2M) + kc * 128;
            bstr = 256;
        }
        const __half* bhp = bh + (size_t)(b * NP + nbase) * bstr;
        const __half* bmp = bm + (size_t)(b * NP + nbase) * bstr;
#pragma unroll
        for (int idx = tid; idx < NT * 16; idx += 256) {
            int row = idx >> 4, ch = idx & 15;
            *(uint4*)(Bs + (size_t)row * CLDA + ch * 8) =
                *(const uint4*)(bhp + (size_t)row * bstr + ch * 8);
            *(uint4*)(Bs + (size_t)row * CLDA + 128 + ch * 8) =
                *(const uint4*)(bmp + (size_t)row * bstr + ch * 8);
        }
        __syncthreads();

#pragma unroll
        for (int k16 = 0; k16 < 8; k16++) {
            int kch = k16 * 16 + lcol8;
            uint32_t ah[4][4], am[4][4], bhf[NI / 2][4], bmf[NI / 2][4];
#pragma unroll
            for (int mi = 0; mi < 4; mi++) {
                uint32_t rb = a_s0 + (uint32_t)(((mi * 16 + lrow) * CLDA) * 2);
                LDSM4(ah[mi], rb + kch * 2);
                LDSM4(am[mi], rb + (128 + kch) * 2);
            }
#pragma unroll
            for (int nh = 0; nh < NI / 2; nh++) {
                uint32_t rb = b_s0 + (uint32_t)(((nh * 16 + lrow) * CLDA) * 2);
                LDSM4(bhf[nh], rb + kch * 2);
                LDSM4(bmf[nh], rb + (128 + kch) * 2);
            }
#pragma unroll
            for (int mi = 0; mi < 4; mi++)
#pragma unroll
                for (int ni = 0; ni < NI; ni++) {
                    uint32_t h0 = bhf[ni >> 1][ni & 1], h1 = bhf[ni >> 1][2 + (ni & 1)];
                    uint32_t m0 = bmf[ni >> 1][ni & 1], m1 = bmf[ni >> 1][2 + (ni & 1)];
                    MMA16816(acc[mi][ni], ah[mi], h0, h1);
                    MMA16816(acc[mi][ni], ah[mi], m0, m1);
                    MMA16816(acc[mi][ni], am[mi], h0, h1);
                }
        }
        __syncthreads();
    }

    int g = lane >> 2, q = lane & 3;
    if (MODE == 0) {
        const float* bias_ = (yb == 0 ? bias0 : yb == 1 ? bias1 : bias2);
        float* patch = (float*)cs + (size_t)wid * 32 * 68;
#pragma unroll
        for (int mi = 0; mi < 4; mi++)
#pragma unroll
            for (int ni = 0; ni < NI; ni++) {
                int rl = mi * 16 + g;
                int cl = ni * 8 + q * 2;
                float bs0 = bias_[mw * 64 + rl], bs1 = bias_[mw * 64 + rl + 8];
                patch[(cl + 0) * 68 + rl]     = acc[mi][ni][0] + bs0;
                patch[(cl + 1) * 68 + rl]     = acc[mi][ni][1] + bs0;
                patch[(cl + 0) * 68 + rl + 8] = acc[mi][ni][2] + bs1;
                patch[(cl + 1) * 68 + rl + 8] = acc[mi][ni][3] + bs1;
            }
        __syncwarp();
        float* Y = g_buf + O_QT + (size_t)yb * BB * NP * CC;
#pragma unroll
        for (int r = 0; r < 32; r++) {
            int n = nbase + nw * 32 + r;
            *(float2*)(Y + ((size_t)b * NP + n) * CC + mw * 64 + lane * 2) =
                *(float2*)(patch + r * 68 + lane * 2);
        }
    } else {
        const float* bias_ = bias0;
        float* Yb = outp + (size_t)b * ((MODE == 2) ? C2 * NP : CC * NP);
#pragma unroll
        for (int mi = 0; mi < 4; mi++)
#pragma unroll
            for (int ni = 0; ni < NI; ni++) {
                int r0 = obase + mw * 64 + mi * 16 + g;
                int c0 = nbase + nw * (NT / 4) + ni * 8 + q * 2;
                float bs0 = bias_[r0], bs1 = bias_[r0 + 8];
                float2 v01, v23;
                v01.x = acc[mi][ni][0] + bs0; v01.y = acc[mi][ni][1] + bs0;
                v23.x = acc[mi][ni][2] + bs1; v23.y = acc[mi][ni][3] + bs1;
                if (MODE == 3) {
                    const float* rb = resid + (size_t)b * CC * NP;
                    v01.x += rb[(size_t)r0 * NP + c0];
                    v01.y += rb[(size_t)r0 * NP + c0 + 1];
                    v23.x += rb[(size_t)(r0 + 8) * NP + c0];
                    v23.y += rb[(size_t)(r0 + 8) * NP + c0 + 1];
                }
                *(float2*)(Yb + (size_t)r0 * NP + c0) = v01;
                *(float2*)(Yb + (size_t)(r0 + 8) * NP + c0) = v23;
            }
    }
}

// ---------------- warp-per-row top-20 (4 rows/block, 128 threads) ----------------
#define TOPK_ROWS 4
#define TOPK_SMEM (TOPK_ROWS * 2048 * 4)
__global__ void __launch_bounds__(128) topk_kernel() {
    extern __shared__ float srows[];
    const unsigned FULL = 0xffffffffu;
    int tid = threadIdx.x, lane = tid & 31, wid = tid >> 5;
    int rowbase = blockIdx.x * TOPK_ROWS;
    const float4* g4 = (const float4*)(g_buf + O_PD + (size_t)rowbase * NP);
    float4* s4 = (float4*)srows;
#pragma unroll
    for (int i = tid; i < TOPK_ROWS * 512; i += 128) s4[i] = g4[i];
    __syncthreads();

    float* s = srows + wid * 2048 + lane * 64;
    float bv = -3.4e38f; int bi = 0;
#pragma unroll
    for (int k4 = 0; k4 < 16; k4++) {
        float4 vv = *(float4*)(s + k4 * 4);
        if (vv.x > bv) { bv = vv.x; bi = k4 * 4 + 0; }
        if (vv.y > bv) { bv = vv.y; bi = k4 * 4 + 1; }
        if (vv.z > bv) { bv = vv.z; bi = k4 * 4 + 2; }
        if (vv.w > bv) { bv = vv.w; bi = k4 * 4 + 3; }
    }
    int gbase = lane * 64;
    int* idxout = reinterpret_cast<int*>(g_buf + O_IDX) + (size_t)(rowbase + wid) * KNN;

    for (int it = 0; it < KNN; it++) {
        float cv = bv; int ci = gbase + bi;
#pragma unroll
        for (int off = 16; off; off >>= 1) {
            float ov = __shfl_down_sync(FULL, cv, off);
            int oi = __shfl_down_sync(FULL, ci, off);
            if (ov > cv || (ov == cv && oi < ci)) { cv = ov; ci = oi; }
        }
        ci = __shfl_sync(FULL, ci, 0);
        if (lane == 0) idxout[it] = ci;
        if ((ci >> 6) == lane) {
            s[ci & 63] = -3.4e38f;
            bv = -3.4e38f; bi = 0;
#pragma unroll
            for (int k4 = 0; k4 < 16; k4++) {
                float4 vv = *(float4*)(s + k4 * 4);
                if (vv.x > bv) { bv = vv.x; bi = k4 * 4 + 0; }
                if (vv.y > bv) { bv = vv.y; bi = k4 * 4 + 1; }
                if (vv.z > bv) { bv = vv.z; bi = k4 * 4 + 2; }
                if (vv.w > bv) { bv = vv.w; bi = k4 * 4 + 3; }
            }
        }
    }
}

// ---------------- sparse mutual-kNN attention: one warp per (b,n) ----------------
__global__ void attn_kernel() {
    const unsigned FULL = 0xffffffffu;
    int gwarp = (blockIdx.x * blockDim.x + threadIdx.x) >> 5;
    int lane = threadIdx.x & 31;
    int b = gwarp / NP, n = gwarp - b * NP;

    const float* qT = g_buf + O_QT;
    const float* kT = g_buf + O_QT + BB * NP * CC;
    const float* vT = g_buf + O_QT + 2 * BB * NP * CC;
    const int* idx = reinterpret_cast<const int*>(g_buf + O_IDX);

    const float* qrow = qT + ((size_t)b * NP + n) * CC;
    float q0 = qrow[lane], q1 = qrow[lane + 32], q2 = qrow[lane + 64], q3 = qrow[lane + 96];

    int mj = 0, act = 0;
    if (lane < KNN) {
        mj = idx[(b * NP + n) * KNN + lane];
        const int* lst = idx + (size_t)(b * NP + mj) * KNN;
#pragma unroll
        for (int tt = 0; tt < KNN; tt++) act |= (lst[tt] == n);
    }
    unsigned amask = __ballot_sync(FULL, act);

    float sc[4] = {0.f, 0.f, 0.f, 0.f};
    for (int jj = 0; jj < KNN; jj++) {
        if (!((amask >> jj) & 1)) continue;
        int m = __shfl_sync(FULL, mj, jj);
        const float* krow = kT + ((size_t)b * NP + m) * CC;
        float p0 = q0 * krow[lane], p1 = q1 * krow[lane + 32];
        float p2 = q2 * krow[lane + 64], p3 = q3 * krow[lane + 96];
#pragma unroll
        for (int off = 16; off; off >>= 1) {
            p0 += __shfl_xor_sync(FULL, p0, off);
            p1 += __shfl_xor_sync(FULL, p1, off);
            p2 += __shfl_xor_sync(FULL, p2, off);
            p3 += __shfl_xor_sync(FULL, p3, off);
        }
        if (lane == jj) { sc[0] = p0; sc[1] = p1; sc[2] = p2; sc[3] = p3; }
    }

    const float scale = 0.17677669529663687f;
    bool live = (lane < KNN) && ((amask >> lane) & 1);
    float p[4];
#pragma unroll
    for (int hh = 0; hh < 4; hh++) {
        float v = live ? sc[hh] * scale : -3.4e38f;
        float mx = v;
#pragma unroll
        for (int off = 16; off; off >>= 1) mx = fmaxf(mx, __shfl_xor_sync(FULL, mx, off));
        float e = live ? expf(v - mx) : 0.f;
        float sm = e;
#pragma unroll
        for (int off = 16; off; off >>= 1) sm += __shfl_xor_sync(FULL, sm, off);
        p[hh] = e / sm;
    }

    float a0 = 0.f, a1 = 0.f, a2 = 0.f, a3 = 0.f;
    for (int jj = 0; jj < KNN; jj++) {
        if (!((amask >> jj) & 1)) continue;
        int m = __shfl_sync(FULL, mj, jj);
        float w0 = __shfl_sync(FULL, p[0], jj);
        float w1 = __shfl_sync(FULL, p[1], jj);
        float w2 = __shfl_sync(FULL, p[2], jj);
        float w3 = __shfl_sync(FULL, p[3], jj);
        const float* vrow = vT + ((size_t)b * NP + m) * CC;
        a0 = fmaf(w0, vrow[lane], a0);
        a1 = fmaf(w1, vrow[lane + 32], a1);
        a2 = fmaf(w2, vrow[lane + 64], a2);
        a3 = fmaf(w3, vrow[lane + 96], a3);
    }
    __half* avh = (__half*)(g_buf + O_AVH);
    __half* avm = (__half*)(g_buf + O_AVM);
    size_t o = ((size_t)b * NP + n) * CC;
    float vals[4] = {a0, a1, a2, a3};
#pragma unroll
    for (int c = 0; c < 4; c++) {
        __half hh = __float2half_rn(vals[c]);
        avh[o + c * 32 + lane] = hh;
        avm[o + c * 32 + lane] = __float2half_rn(vals[c] - __half2float(hh));
    }
}

// ---------------- batchnorm statistics ----------------
__global__ void bn_stats_kernel() {
    __shared__ float ss[256], ss2[256];
    int c = blockIdx.x, tid = threadIdx.x;
    float s = 0.f, s2 = 0.f;
    for (int bn = tid; bn < BB * NP; bn += 256) {
        int b = bn >> 11, n = bn & (NP - 1);
        float v = g_buf[O_H + (size_t)b * C2 * NP + (size_t)c * NP + n];
        s += v; s2 = fmaf(v, v, s2);
    }
    ss[tid] = s; ss2[tid] = s2;
    __syncthreads();
    for (int off = 128; off; off >>= 1) {
        if (tid < off) { ss[tid] += ss[tid + off]; ss2[tid] += ss2[tid + off]; }
        __syncthreads();
    }
    if (tid == 0) {
        float inv = 1.f / (BB * NP);
        float mu = ss[0] * inv;
        float var = ss2[0] * inv - mu * mu;
        g_buf[O_MU + c] = mu;
        g_buf[O_ISTD + c] = rsqrtf(var + 1e-5f);
    }
}

// ---------------- bn+relu + transpose + split ----------------
__global__ void bnrelu_kernel(const float* __restrict__ gamma, const float* __restrict__ beta) {
    __shared__ float t[32][33];
    int b = blockIdx.z, cbase = blockIdx.y * 32, nbase = blockIdx.x * 32;
    int tid = threadIdx.x;
    const float* hsrc = g_buf + O_H + (size_t)b * C2 * NP;
#pragma unroll
    for (int i = tid; i < 1024; i += 256) {
        int c = i >> 5, n = i & 31;
        t[c][n] = hsrc[(size_t)(cbase + c) * NP + nbase + n];
    }
    __syncthreads();
    __half* h2h = (__half*)(g_buf + O_H2H);
    __half* h2m = (__half*)(g_buf + O_H2M);
#pragma unroll
    for (int i = tid; i < 1024; i += 256) {
        int n = i >> 5, c = i & 31;
        int cg = cbase + c;
        float v = t[c][n];
        v = fmaxf(fmaf((v - g_buf[O_MU + cg]) * g_buf[O_ISTD + cg], gamma[cg], beta[cg]), 0.f);
        __half hh = __float2half_rn(v);
        size_t o = ((size_t)b * NP + nbase + n) * C2 + cg;
        h2h[o] = hh;
        h2m[o] = __float2half_rn(v - __half2float(hh));
    }
}

// ---------------- launch ----------------
extern "C" void kernel_launch(void* const* d_in, const int* in_sizes, int n_in,
                              void* d_out, int out_size) {
    (void)in_sizes; (void)n_in; (void)out_size;
    const float* x     = (const float*)d_in[0];
    const float* wq    = (const float*)d_in[1];
    const float* bq    = (const float*)d_in[2];
    const float* wk    = (const float*)d_in[3];
    const float* bk    = (const float*)d_in[4];
    const float* wv    = (const float*)d_in[5];
    const float* bv    = (const float*)d_in[6];
    const float* wm    = (const float*)d_in[7];
    const float* bm    = (const float*)d_in[8];
    const float* w1    = (const float*)d_in[9];
    const float* b1    = (const float*)d_in[10];
    const float* gamma = (const float*)d_in[11];
    const float* beta  = (const float*)d_in[12];
    const float* w2    = (const float*)d_in[13];
    const float* b2    = (const float*)d_in[14];
    float* out = (float*)d_out;

    float* base = nullptr;
    cudaGetSymbolAddress((void**)&base, g_buf);
    float* p_h = base + O_H;
    float* p_b1p = base + O_B1P;

    static cudaStream_t s2 = nullptr, s3 = nullptr;
    static cudaEvent_t evFork = nullptr, evPrep = nullptr, evXX = nullptr,
                       evQKV = nullptr, evW = nullptr;
    if (s2 == nullptr) {
        cudaStreamCreateWithFlags(&s2, cudaStreamNonBlocking);
        cudaStreamCreateWithFlags(&s3, cudaStreamNonBlocking);
        cudaEventCreateWithFlags(&evFork, cudaEventDisableTiming);
        cudaEventCreateWithFlags(&evPrep, cudaEventDisableTiming);
        cudaEventCreateWithFlags(&evXX, cudaEventDisableTiming);
        cudaEventCreateWithFlags(&evQKV, cudaEventDisableTiming);
        cudaEventCreateWithFlags(&evW, cudaEventDisableTiming);
    }

    cudaFuncSetAttribute(pd_mma_kernel, cudaFuncAttributeMaxDynamicSharedMemorySize, PD_SMEM);
    cudaFuncSetAttribute(conv_mma<0>, cudaFuncAttributeMaxDynamicSharedMemorySize, CONV_SMEM0);
    cudaFuncSetAttribute(conv_mma<2>, cudaFuncAttributeMaxDynamicSharedMemorySize, CONV_SMEM64);
    cudaFuncSetAttribute(conv_mma<3>, cudaFuncAttributeMaxDynamicSharedMemorySize, CONV_SMEM64);
    cudaFuncSetAttribute(topk_kernel, cudaFuncAttributeMaxDynamicSharedMemorySize, TOPK_SMEM);

    // fork point
    cudaEventRecord(evFork, 0);
    cudaStreamWaitEvent(s2, evFork, 0);
    cudaStreamWaitEvent(s3, evFork, 0);

    // s2: weight split -> (wait prep) qkv conv -> weight fuse
    wsplit_kernel<<<(WTOT + 255) / 256, 256, 0, s2>>>(wq, wk, wv, wm, w1, w2);
    // s3: xx
    xx_kernel<<<(BB * NP + 255) / 256, 256, 0, s3>>>(x);
    cudaEventRecord(evXX, s3);
    // main: prep
    prep_kernel<<<dim3(NP / 64, CC / 32, BB), 256>>>(x);
    cudaEventRecord(evPrep, 0);

    cudaStreamWaitEvent(s2, evPrep, 0);
    conv_mma<0><<<dim3(NP / 128, 3, BB), 256, CONV_SMEM0, s2>>>(bq, bk, bv, nullptr, nullptr);
    cudaEventRecord(evQKV, s2);
    wfuse_kernel<<<256, 128, 0, s2>>>(w1, wm, bm, b1);
    cudaEventRecord(evW, s2);

    // main: pd -> topk (needs prep + xx)
    cudaStreamWaitEvent(0, evXX, 0);
    pd_mma_kernel<<<dim3(136, BB), 256, PD_SMEM>>>();
    topk_kernel<<<BB * NP / TOPK_ROWS, 128, TOPK_SMEM>>>();

    cudaStreamWaitEvent(0, evQKV, 0);
    attn_kernel<<<BB * NP / 8, 256>>>();

    cudaStreamWaitEvent(0, evW, 0);
    conv_mma<2><<<dim3(NP / 64, 2, BB), 256, CONV_SMEM64>>>(p_b1p, nullptr, nullptr, nullptr, p_h);

    bn_stats_kernel<<<C2, 256>>>();
    bnrelu_kernel<<<dim3(NP / 32, C2 / 32, BB), 256>>>(gamma, beta);

    conv_mma<3><<<dim3(NP / 64, 1, BB), 256, CONV_SMEM64>>>(b2, nullptr, nullptr, x, out);
}